// round 10
// baseline (speedup 1.0000x reference)
#include <cuda_runtime.h>
#include <cuda_bf16.h>
#include <math.h>
#include <stdint.h>

#define NBATCH 4
#define NCH    180
#define IMG    256
#define NPIX   (IMG*IMG)            // 65536
#define TOTPIX (NBATCH*NPIX)        // 262144
#define MIDC   36
#define NWIN   1024

// ---- scratch (device globals; no allocation allowed) ----
__device__ float g_h1[(size_t)TOTPIX*MIDC];
__device__ float g_h2[(size_t)TOTPIX*MIDC];
__device__ float g_qv[(size_t)TOTPIX*NCH];
__device__ float g_y [(size_t)TOTPIX*NCH];
__device__ float g_pos[961*6];
__device__ float g_rpb[6*256*64];
__device__ __align__(16) __nv_bfloat16 g_pk_lw[6*13824];
__device__ __align__(16) __nv_bfloat16 g_pk_pj[6*13824];
__device__ __align__(16) __nv_bfloat16 g_pk_w3[2*10752];

typedef unsigned long long u64;

__device__ __forceinline__ u64 pk2(float lo, float hi){
  u64 r; asm("mov.b64 %0,{%1,%2};" : "=l"(r) : "f"(lo), "f"(hi)); return r;
}
__device__ __forceinline__ u64 dup2(float v){ return pk2(v, v); }
__device__ __forceinline__ void up2(u64 v, float& lo, float& hi){
  asm("mov.b64 {%0,%1},%2;" : "=f"(lo), "=f"(hi) : "l"(v));
}
__device__ __forceinline__ u64 ffma2(u64 a, u64 b, u64 c){
  u64 d; asm("fma.rn.f32x2 %0,%1,%2,%3;" : "=l"(d) : "l"(a), "l"(b), "l"(c)); return d;
}
__device__ __forceinline__ u64 fmul2(u64 a, u64 b){
  u64 d; asm("mul.rn.f32x2 %0,%1,%2;" : "=l"(d) : "l"(a), "l"(b)); return d;
}
__device__ __forceinline__ float lrelu(float v){ return v >= 0.f ? v : 0.2f*v; }

__device__ __forceinline__ void cvhl(float v, __nv_bfloat16& h, __nv_bfloat16& l){
  h = __float2bfloat16(v);
  l = __float2bfloat16(v - __bfloat162float(h));
}

// ---- portable tensor-core primitives ----
#define MMA16816(c, a, b0, b1) \
  asm volatile("mma.sync.aligned.m16n8k16.row.col.f32.bf16.bf16.f32 " \
    "{%0,%1,%2,%3}, {%4,%5,%6,%7}, {%8,%9}, {%0,%1,%2,%3};" \
    : "+f"((c)[0]), "+f"((c)[1]), "+f"((c)[2]), "+f"((c)[3]) \
    : "r"((a)[0]), "r"((a)[1]), "r"((a)[2]), "r"((a)[3]), "r"(b0), "r"(b1))

__device__ __forceinline__ void ldsm_x4(uint32_t r[4], uint32_t saddr){
  asm volatile("ldmatrix.sync.aligned.m8n8.x4.shared.b16 {%0,%1,%2,%3}, [%4];"
    : "=r"(r[0]),"=r"(r[1]),"=r"(r[2]),"=r"(r[3]) : "r"(saddr));
}
__device__ __forceinline__ void cpa16(uint32_t d, const void* s){
  asm volatile("cp.async.cg.shared.global [%0], [%1], 16;" :: "r"(d), "l"(s));
}
#define CP_COMMIT() asm volatile("cp.async.commit_group;" ::: "memory")
#define CP_WAIT(n)  asm volatile("cp.async.wait_group %0;" :: "n"(n) : "memory")

template<int SA, int SB, int NKS>
__device__ __forceinline__ void mma_pass(uint32_t aBase, uint32_t bBase,
                                         float c[2][6][4], int lane, int wm, int wn){
  uint32_t aoff[2], boff[3];
  int ar = (lane&7) + ((lane&8)?8:0);
  int ak = (lane&16)?8:0;
#pragma unroll
  for (int mt=0;mt<2;mt++) aoff[mt] = aBase + (uint32_t)(((wm*32+mt*16+ar)*SA + ak)*2);
  int br = (lane&7) + ((lane&16)?8:0);
  int bk = (lane&8)?8:0;
#pragma unroll
  for (int p=0;p<3;p++) boff[p] = bBase + (uint32_t)(((wn*48+p*16+br)*SB + bk)*2);

  uint32_t a[2][2][4], b[2][3][4];
  ldsm_x4(a[0][0], aoff[0]);
  ldsm_x4(a[0][1], aoff[1]);
#pragma unroll
  for (int p=0;p<3;p++) ldsm_x4(b[0][p], boff[p]);
#pragma unroll
  for (int ks=0;ks<NKS;ks++){
    int cur = ks&1, nxt = cur^1;
    if (ks+1 < NKS){
      ldsm_x4(a[nxt][0], aoff[0] + (ks+1)*32);
      ldsm_x4(a[nxt][1], aoff[1] + (ks+1)*32);
#pragma unroll
      for (int p=0;p<3;p++) ldsm_x4(b[nxt][p], boff[p] + (ks+1)*32);
    }
#pragma unroll
    for (int p=0;p<3;p++){
      MMA16816(c[0][2*p],   a[cur][0], b[cur][p][0], b[cur][p][1]);
      MMA16816(c[1][2*p],   a[cur][1], b[cur][p][0], b[cur][p][1]);
      MMA16816(c[0][2*p+1], a[cur][0], b[cur][p][2], b[cur][p][3]);
      MMA16816(c[1][2*p+1], a[cur][1], b[cur][p][2], b[cur][p][3]);
    }
  }
}

__device__ __forceinline__ void ln_relu11(const float* in, const float* w, const float* b, float* out){
  float m = 0.f;
#pragma unroll
  for (int j=0;j<11;j++) m += in[j];
  m *= (1.f/11.f);
  float var = 0.f;
#pragma unroll
  for (int j=0;j<11;j++){ float d = in[j]-m; var += d*d; }
  var *= (1.f/11.f);
  float inv = rsqrtf(var + 1e-5f);
#pragma unroll
  for (int j=0;j<11;j++) out[j] = fmaxf((in[j]-m)*inv*w[j] + b[j], 0.f);
}

// =============== MEGA1 ===============
__global__ void __launch_bounds__(256) mega1(
    const float* __restrict__ x,  const float* __restrict__ w1, const float* __restrict__ b1,
    const float* __restrict__ lw, const float* __restrict__ pjw, const float* __restrict__ w3,
    const float* __restrict__ pw, const float* __restrict__ pb,
    const float* __restrict__ ln1w, const float* __restrict__ ln1b,
    const float* __restrict__ p1w,  const float* __restrict__ p1b,
    const float* __restrict__ ln2w, const float* __restrict__ ln2b,
    const float* __restrict__ p2w,  const float* __restrict__ p2b,
    const float* __restrict__ ln3w, const float* __restrict__ ln3b,
    const float* __restrict__ p3w,  const float* __restrict__ p3b){
  __shared__ __align__(16) float ws[180*36];
  int gid = blockIdx.x;
  int tid = threadIdx.x;

  if (gid < 1024){
    for (int t=tid;t<180*36;t+=256) ws[t]=w1[t];
    __syncthreads();
    int r = gid*256 + tid;
    int b = r>>16; int p = r&65535;
    const float* xp = x + (size_t)b*NCH*NPIX + p;
    u64 acc2[18];
#pragma unroll
    for (int q=0;q<18;q++) acc2[q] = pk2(b1[2*q], b1[2*q+1]);
    for (int ci=0;ci<180;ci++){
      u64 v2 = dup2(xp[(size_t)ci*NPIX]);
      const ulonglong2* wr = (const ulonglong2*)(ws + ci*36);
#pragma unroll
      for (int q=0;q<9;q++){
        ulonglong2 w = wr[q];
        acc2[2*q]   = ffma2(v2, w.x, acc2[2*q]);
        acc2[2*q+1] = ffma2(v2, w.y, acc2[2*q+1]);
      }
    }
    float2* dst = (float2*)(g_h1 + (size_t)r*36);
#pragma unroll
    for (int q=0;q<18;q++){
      float lo,hi; up2(acc2[q], lo, hi);
      dst[q] = make_float2(lrelu(lo), lrelu(hi));
    }
  } else if (gid < 1672){
    int which = (gid >= 1348);
    const float* W = which ? pjw : lw;
    __nv_bfloat16* dst = which ? g_pk_pj : g_pk_lw;
    int base = which ? 1348 : 1024;
    int idx = (gid-base)*256 + tid;
    if (idx < 6*13824){
      int cc = idx/13824, r = idx - cc*13824, n = r/72, k = r - n*72;
      int half = cc/3, kc = cc - half*3;
      int kk = kc*64 + k;
      float v = (n<180 && k<64 && kk<180) ? W[kk*180+n] : 0.f;
      __nv_bfloat16 h, l; cvhl(v, h, l);
      dst[idx] = half ? l : h;
    }
  } else if (gid < 1756){
    int idx = (gid-1672)*256 + tid;
    if (idx < 2*10752){
      int cc = idx/10752, r = idx - cc*10752, n = r/56, k = r - n*56;
      float v = (n<180 && k<36) ? w3[k*180+n] : 0.f;
      __nv_bfloat16 h, l; cvhl(v, h, l);
      g_pk_w3[idx] = cc ? l : h;
    }
  } else {
    int n = (gid-1756)*256 + tid;
    if (n < 961){
      float i0 = (float)(n/31) - 15.f;
      float i1 = (float)(n%31) - 15.f;
      float p[11], t[11];
#pragma unroll
      for (int j=0;j<11;j++) p[j] = i0*pw[j] + i1*pw[11+j] + pb[j];
      ln_relu11(p, ln1w, ln1b, t);
#pragma unroll
      for (int k=0;k<11;k++){ float s=p1b[k];
#pragma unroll
        for (int j=0;j<11;j++) s += t[j]*p1w[j*11+k]; p[k]=s; }
      ln_relu11(p, ln2w, ln2b, t);
#pragma unroll
      for (int k=0;k<11;k++){ float s=p2b[k];
#pragma unroll
        for (int j=0;j<11;j++) s += t[j]*p2w[j*11+k]; p[k]=s; }
      ln_relu11(p, ln3w, ln3b, t);
#pragma unroll
      for (int k=0;k<6;k++){ float s=p3b[k];
#pragma unroll
        for (int j=0;j<11;j++) s += t[j]*p3w[j*6+k];
        g_pos[n*6+k] = s; }
    }
  }
}

// =============== MEGA2: t_lin + conv3 + rpb ===============
__global__ void __launch_bounds__(256,2) mega2(const float* __restrict__ x,
                                               const float* __restrict__ lb,
                                               const float* __restrict__ w2,
                                               const float* __restrict__ b2){
  extern __shared__ __align__(16) char smc[];
  int gid = blockIdx.x;
  int tid = threadIdx.x;

  if (gid < 4096){
    __nv_bfloat16* Ab = (__nv_bfloat16*)smc;
    const uint32_t O_B0 = 6*4608*2, O_B1 = O_B0 + 13824*2;
    uint32_t sbase = (uint32_t)__cvta_generic_to_shared(smc);
    int lane = tid&31, wid = tid>>5;
    int wm = wid&1, wn = wid>>1;
    int r0 = gid*64; int bb = r0>>16; int p0 = r0&65535;

    for (int t=tid; t<1728; t+=256)
      cpa16(sbase + O_B0 + t*16, (const char*)(g_pk_lw) + t*16);
    CP_COMMIT();

    for (int idx=tid; idx<192*64; idx+=256){
      int c = idx>>6, px = idx&63;
      float v = (c<180) ? x[((size_t)(bb*180+c))*NPIX + p0+px] : 0.f;
      __nv_bfloat16 h,l; cvhl(v,h,l);
      int t = c>>6, k = c&63;
      Ab[t*4608 + px*72 + k]     = h;
      Ab[(t+3)*4608 + px*72 + k] = l;
    }
    float c[2][6][4];
#pragma unroll
    for (int mt=0;mt<2;mt++)
#pragma unroll
      for (int nt=0;nt<6;nt++)
#pragma unroll
        for (int e=0;e<4;e++) c[mt][nt][e]=0.f;

    for (int i=0;i<6;i++){
      uint32_t bo = (i&1) ? O_B1 : O_B0;
      if (i<5){
        uint32_t bn = ((i+1)&1) ? O_B1 : O_B0;
        for (int t=tid; t<1728; t+=256)
          cpa16(sbase + bn + t*16, (const char*)(g_pk_lw + (i+1)*13824) + t*16);
        CP_COMMIT();
        CP_WAIT(1);
      } else {
        CP_WAIT(0);
      }
      __syncthreads();
      if (i<3){
        mma_pass<72,72,4>(sbase + (uint32_t)(i*4608*2),     sbase + bo, c, lane, wm, wn);
        mma_pass<72,72,4>(sbase + (uint32_t)((3+i)*4608*2), sbase + bo, c, lane, wm, wn);
      } else {
        mma_pass<72,72,4>(sbase + (uint32_t)((i-3)*4608*2), sbase + bo, c, lane, wm, wn);
      }
      __syncthreads();
    }
    float* stash = (float*)smc;
#pragma unroll
    for (int mt=0;mt<2;mt++){
      int r1 = wm*32 + mt*16 + (lane>>2);
#pragma unroll
      for (int nt=0;nt<6;nt++){
        int n0 = wn*48 + nt*8 + (lane&3)*2;
        if (n0 < 180){
          float bl0=__ldg(lb+n0), bl1=__ldg(lb+n0+1);
          stash[r1*181+n0]       = c[mt][nt][0]+bl0;
          stash[r1*181+n0+1]     = c[mt][nt][1]+bl1;
          stash[(r1+8)*181+n0]   = c[mt][nt][2]+bl0;
          stash[(r1+8)*181+n0+1] = c[mt][nt][3]+bl1;
        }
      }
    }
    __syncthreads();
    int f = tid;
    int px = f/180, co = f - px*180;
    for (; f < 64*180; f += 256){
      g_y[(size_t)r0*180 + f] = stash[px*181+co];
      co += 256; if (co >= 180){ co -= 180; px++; if (co >= 180){ co -= 180; px++; } }
    }
  } else if (gid < 5120){
    float* ins = (float*)smc;
    float* wsh = (float*)smc + 11988;
    int cg = gid - 4096;
    int b = cg>>8; int hy0 = ((cg>>4)&15)*16, wx0 = (cg&15)*16;
    for (int t=tid;t<18*18*36;t+=256){
      int ci = t%36; int rc = t/36; int col = rc%18; int row = rc/18;
      int gh = hy0+row-1, gw = wx0+col-1;
      float v = 0.f;
      if (gh>=0 && gh<IMG && gw>=0 && gw<IMG)
        v = g_h1[((size_t)(b*IMG+gh)*IMG+gw)*36 + ci];
      ins[(row*18+col)*37+ci] = v;
    }
    for (int t=tid;t<9*36*36;t+=256) wsh[t] = w2[t];
    __syncthreads();
    int tx = tid&15, ty = tid>>4;
    float acc[36];
#pragma unroll
    for (int co=0;co<36;co++) acc[co] = b2[co];
    for (int dy=0;dy<3;dy++)
      for (int dx=0;dx<3;dx++){
        const float* wp = wsh + (dy*3+dx)*36*36;
        const float* ip = ins + ((ty+dy)*18 + tx+dx)*37;
        for (int ci=0;ci<36;ci++){
          float v = ip[ci];
          const float* wr = wp + ci*36;
#pragma unroll
          for (int co=0;co<36;co++) acc[co] += v*wr[co];
        }
      }
    size_t o = ((size_t)(b*IMG+hy0+ty)*IMG + wx0+tx)*36;
    float4* dst = (float4*)(g_h2 + o);
#pragma unroll
    for (int q=0;q<9;q++){
      float4 r; r.x=lrelu(acc[q*4]); r.y=lrelu(acc[q*4+1]); r.z=lrelu(acc[q*4+2]); r.w=lrelu(acc[q*4+3]);
      dst[q]=r;
    }
  } else {
    int idx = (gid-5120)*256 + tid;
    if (idx < 6*256*64){
      int nh = idx/16384;
      int r  = idx - nh*16384;
      int l  = r>>6;
      int m  = r&63;
      int rl = l>>4, cl = l&15;
      int mh = m>>3, mw = m&7;
      float s = 0.f;
#pragma unroll
      for (int rh=0;rh<2;rh++)
#pragma unroll
        for (int rw=0;rw<2;rw++){
          int r2 = mh*2+rh, c2 = mw*2+rw;
          int k = (rl-r2+15)*31 + (cl-c2+15);
          s += g_pos[k*6+nh];
        }
      g_rpb[idx] = 0.25f*s;
    }
  }
}

// =============== T2: t_h3 ===============
__global__ void __launch_bounds__(256,2) t_h3(const float* __restrict__ b3){
  extern __shared__ __align__(16) char smc[];
  __nv_bfloat16* Ab = (__nv_bfloat16*)smc;
  const uint32_t O_B = 7168*2;
  uint32_t sbase = (uint32_t)__cvta_generic_to_shared(smc);
  int tid = threadIdx.x; int lane = tid&31, wid = tid>>5;
  int wm = wid&1, wn = wid>>1;
  int r0 = blockIdx.x*64;

  for (int t=tid; t<2688; t+=256)
    cpa16(sbase + O_B + t*16, (const char*)(g_pk_w3) + t*16);
  CP_COMMIT();

  for (int idx=tid; idx<64*48; idx+=256){
    int px = idx/48, cc = idx - px*48;
    float v = (cc<36) ? g_h2[(size_t)(r0+px)*36 + cc] : 0.f;
    __nv_bfloat16 h,l; cvhl(v,h,l);
    Ab[px*56 + cc]        = h;
    Ab[3584 + px*56 + cc] = l;
  }
  CP_WAIT(0);
  __syncthreads();
  float c[2][6][4];
#pragma unroll
  for (int mt=0;mt<2;mt++)
#pragma unroll
    for (int nt=0;nt<6;nt++)
#pragma unroll
      for (int e=0;e<4;e++) c[mt][nt][e]=0.f;

  mma_pass<56,56,3>(sbase,           sbase + O_B,           c, lane, wm, wn);
  mma_pass<56,56,3>(sbase + 3584*2,  sbase + O_B,           c, lane, wm, wn);
  mma_pass<56,56,3>(sbase,           sbase + O_B + 10752*2, c, lane, wm, wn);
  __syncthreads();
  float* stash = (float*)smc;
#pragma unroll
  for (int mt=0;mt<2;mt++){
    int r1 = wm*32 + mt*16 + (lane>>2);
#pragma unroll
    for (int nt=0;nt<6;nt++){
      int n0 = wn*48 + nt*8 + (lane&3)*2;
      if (n0 < 180){
        float b30=__ldg(b3+n0), b31=__ldg(b3+n0+1);
        stash[r1*181+n0]       = c[mt][nt][0]+b30;
        stash[r1*181+n0+1]     = c[mt][nt][1]+b31;
        stash[(r1+8)*181+n0]   = c[mt][nt][2]+b30;
        stash[(r1+8)*181+n0+1] = c[mt][nt][3]+b31;
      }
    }
  }
  __syncthreads();
  {
    int f = tid;
    int px = f/180, co = f - px*180;
    for (; f < 64*180; f += 256){
      g_qv[(size_t)r0*180 + f] = stash[px*181+co] * g_y[(size_t)r0*180 + f];
      co += 256; if (co >= 180){ co -= 180; px++; if (co >= 180){ co -= 180; px++; } }
    }
  }
}

// =============== attn_sp: spatial attention (vp-only smem, high occupancy) ===============
__global__ void __launch_bounds__(256,3) attn_sp(const float* __restrict__ sl_w,
                                                 const float* __restrict__ sl_b){
  __shared__ float vp[6144];
  int tid = threadIdx.x;
  int l = tid;
  int bw = blockIdx.x;
  int b = bw>>8, wy = (bw>>4)&15, wx = bw&15;
  size_t pix0 = ((size_t)(b*IMG + wy*16))*IMG + wx*16;
  size_t pix  = pix0 + (size_t)(l>>4)*IMG + (l&15);

  // P2: vp from global V
  float slw0=__ldg(sl_w), slw1=__ldg(sl_w+1), slw2=__ldg(sl_w+2), slw3=__ldg(sl_w+3), slb=__ldg(sl_b);
  for (int idx=tid; idx<6144; idx+=256){
    int nh = idx>>10; int r = idx & 1023; int m = r>>4; int hd = r&15;
    float val = 0.f;
    if (hd < 15){
      int mh = m>>3, mw = m&7; int ch = 90 + nh*15 + hd;
      size_t pA = pix0 + (size_t)(mh*2)*IMG + mw*2;
      val = slb + slw0*__ldg(g_qv + pA*180 + ch)
                + slw1*__ldg(g_qv + (pA+1)*180 + ch)
                + slw2*__ldg(g_qv + (pA+IMG)*180 + ch)
                + slw3*__ldg(g_qv + (pA+IMG+1)*180 + ch);
    }
    vp[idx] = val;
  }
  __syncthreads();

  // P4: 6 heads per thread, q from global
  float* ydst = g_y + pix*180;
  const float* qrow = g_qv + pix*180;
  for (int nh=0; nh<6; nh++){
    float qs[15];
#pragma unroll
    for (int hd=0;hd<15;hd++) qs[hd] = __ldg(qrow + nh*15 + hd);
    u64 q2[8];
#pragma unroll
    for (int p=0;p<7;p++) q2[p] = pk2(qs[2*p], qs[2*p+1]);
    q2[7] = pk2(qs[14], 0.f);
    const float* vph = vp + (nh<<10);
    const float* rpbrow = g_rpb + ((size_t)((nh<<8) + l))*64;
    u64 xs2[8];
#pragma unroll
    for (int p=0;p<8;p++) xs2[p]=0ull;
    for (int m0=0;m0<64;m0+=4){
      float4 rb = *(const float4*)(rpbrow + m0);
      float rbv[4] = {rb.x, rb.y, rb.z, rb.w};
#pragma unroll
      for (int t=0;t<4;t++){
        const ulonglong2* vpp = (const ulonglong2*)(vph + ((m0+t)<<4));
        ulonglong2 wA = vpp[0], wB = vpp[1], wC = vpp[2], wD = vpp[3];
        u64 d2 = fmul2(q2[0], wA.x);
        d2 = ffma2(q2[1], wA.y, d2);
        d2 = ffma2(q2[2], wB.x, d2);
        d2 = ffma2(q2[3], wB.y, d2);
        d2 = ffma2(q2[4], wC.x, d2);
        d2 = ffma2(q2[5], wC.y, d2);
        d2 = ffma2(q2[6], wD.x, d2);
        d2 = ffma2(q2[7], wD.y, d2);
        float lo,hi; up2(d2, lo, hi);
        u64 s2 = dup2((lo+hi)*(1.f/15.f) + rbv[t]);
        xs2[0] = ffma2(s2, wA.x, xs2[0]);
        xs2[1] = ffma2(s2, wA.y, xs2[1]);
        xs2[2] = ffma2(s2, wB.x, xs2[2]);
        xs2[3] = ffma2(s2, wB.y, xs2[3]);
        xs2[4] = ffma2(s2, wC.x, xs2[4]);
        xs2[5] = ffma2(s2, wC.y, xs2[5]);
        xs2[6] = ffma2(s2, wD.x, xs2[6]);
        xs2[7] = ffma2(s2, wD.y, xs2[7]);
      }
    }
#pragma unroll
    for (int p=0;p<7;p++){
      float lo,hi; up2(xs2[p], lo, hi);
      ydst[nh*15+2*p] = lo; ydst[nh*15+2*p+1] = hi;
    }
    { float lo,hi; up2(xs2[7], lo, hi); ydst[nh*15+14] = lo; }
  }
}

// =============== attn_ch: channel attention via mma (cmap + xc) ===============
// phase1 smem: Qh@0 Ql@50688 Vh@101376 Vl@152064  (each 96 rows x 264 bf16 = 50688B)
// phase2 smem: Vph@0 Vpl@53248 (256x104), Cmh@106496 Cml@126464 (96x104)
__global__ void __launch_bounds__(512) attn_ch(){
  extern __shared__ __align__(16) char smc[];
  uint32_t sbase = (uint32_t)__cvta_generic_to_shared(smc);
  __nv_bfloat16* sm16 = (__nv_bfloat16*)smc;
  int tid = threadIdx.x; int lane = tid&31; int w = tid>>5;
  int bw = blockIdx.x;
  int b = bw>>8, wy = (bw>>4)&15, wx = bw&15;
  size_t pix0 = ((size_t)(b*IMG + wy*16))*IMG + wx*16;

  const int QH=0, QL=25344, VH=50688, VL=76032;        // in bf16 elems
  // phase1 load/transpose: warp w handles rows px = w*16 + i
  for (int i=0;i<16;i++){
    int px = w*16 + i;
    size_t pix = pix0 + (size_t)(px>>4)*IMG + (px&15);
    const float* row = g_qv + pix*180;
    for (int c=lane; c<180; c+=32){
      float v = row[c];
      __nv_bfloat16 h,l; cvhl(v,h,l);
      if (c < 90){
        sm16[QH + c*264 + px] = h;
        sm16[QL + c*264 + px] = l;
      } else {
        sm16[VH + (c-90)*264 + px] = h;
        sm16[VL + (c-90)*264 + px] = l;
      }
    }
  }
  // zero pad rows 90..95 of all four tiles
  for (int t=tid; t<6*264; t+=512){
    int rr = 90 + t/264, cc = t%264;
    sm16[QH + rr*264 + cc] = __nv_bfloat16(0.f);
    sm16[QL + rr*264 + cc] = __nv_bfloat16(0.f);
    sm16[VH + rr*264 + cc] = __nv_bfloat16(0.f);
    sm16[VL + rr*264 + cc] = __nv_bfloat16(0.f);
  }
  __syncthreads();

  // phase1 MMA: cmap[c][d] = sum_l Q[l][c] V[l][d]; 12 warps: wm=w>>1 (c/16), wn=w&1 (d/48)
  float c1[6][4];
#pragma unroll
  for (int nt=0;nt<6;nt++)
#pragma unroll
    for (int e=0;e<4;e++) c1[nt][e]=0.f;
  if (w < 12){
    int wm = w>>1, wn = w&1;
    int ar = (lane&7) + ((lane&8)?8:0);
    int ak = (lane&16)?8:0;
    int br = (lane&7) + ((lane&16)?8:0);
    int bk = (lane&8)?8:0;
    const int passes[3][2] = {{QH,VH},{QL,VH},{QH,VL}};
#pragma unroll
    for (int ps=0; ps<3; ps++){
      uint32_t aoff = sbase + (uint32_t)((passes[ps][0] + (wm*16+ar)*264 + ak)*2);
      uint32_t boff[3];
#pragma unroll
      for (int p=0;p<3;p++)
        boff[p] = sbase + (uint32_t)((passes[ps][1] + (wn*48+p*16+br)*264 + bk)*2);
      for (int ks=0;ks<16;ks++){
        uint32_t a4[4];
        ldsm_x4(a4, aoff + ks*32);
#pragma unroll
        for (int p=0;p<3;p++){
          uint32_t b4[4];
          ldsm_x4(b4, boff[p] + ks*32);
          MMA16816(c1[2*p],   a4, b4[0], b4[1]);
          MMA16816(c1[2*p+1], a4, b4[2], b4[3]);
        }
      }
    }
  }
  __syncthreads();

  // phase2 staging: zero cmap region, load Vpix
  const int VPH=0, VPL=26624, CMH=53248, CML=63232;   // bf16 elems
  for (int t=tid; t<2*96*104; t+=512){
    sm16[CMH + t] = __nv_bfloat16(0.f);   // covers CMH then CML (contiguous)
  }
  for (int i=0;i<16;i++){
    int px = w*16 + i;
    size_t pix = pix0 + (size_t)(px>>4)*IMG + (px&15);
    const float* row = g_qv + pix*180 + 90;
    for (int d=lane; d<104; d+=32){
      float v = (d<90) ? row[d] : 0.f;
      __nv_bfloat16 h,l; cvhl(v,h,l);
      sm16[VPH + px*104 + d] = h;
      sm16[VPL + px*104 + d] = l;
    }
  }
  __syncthreads();

  // write cmap frags (scaled 1/256) to smem hi/lo
  if (w < 12){
    int wm = w>>1, wn = w&1;
    int c0 = wm*16 + (lane>>2);
#pragma unroll
    for (int nt=0;nt<6;nt++){
      int d0 = wn*48 + nt*8 + (lane&3)*2;
      if (d0 < 90){
#pragma unroll
        for (int half=0; half<2; half++){
          int cc = c0 + half*8;
          if (cc < 90){
            float v0 = c1[nt][half*2]   * (1.f/256.f);
            float v1 = c1[nt][half*2+1] * (1.f/256.f);
            __nv_bfloat16 h0,l0,h1,l1; cvhl(v0,h0,l0); cvhl(v1,h1,l1);
            sm16[CMH + cc*104 + d0]   = h0;
            sm16[CMH + cc*104 + d0+1] = h1;
            sm16[CML + cc*104 + d0]   = l0;
            sm16[CML + cc*104 + d0+1] = l1;
          }
        }
      }
    }
  }
  __syncthreads();

  // phase2 MMA: xc[l][c] = sum_d V[l][d] cmap[c][d]; 16 warps, m-tile = w*16
  float c2[12][4];
#pragma unroll
  for (int nt=0;nt<12;nt++)
#pragma unroll
    for (int e=0;e<4;e++) c2[nt][e]=0.f;
  {
    int ar = (lane&7) + ((lane&8)?8:0);
    int ak = (lane&16)?8:0;
    int br = (lane&7) + ((lane&16)?8:0);
    int bk = (lane&8)?8:0;
    const int passes[3][2] = {{VPH,CMH},{VPL,CMH},{VPH,CML}};
#pragma unroll
    for (int ps=0; ps<3; ps++){
      uint32_t aoff = sbase + (uint32_t)((passes[ps][0] + (w*16+ar)*104 + ak)*2);
      uint32_t boff[6];
#pragma unroll
      for (int p=0;p<6;p++)
        boff[p] = sbase + (uint32_t)((passes[ps][1] + (p*16+br)*104 + bk)*2);
      for (int ks=0;ks<6;ks++){
        uint32_t a4[4];
        ldsm_x4(a4, aoff + ks*32);
#pragma unroll
        for (int p=0;p<6;p++){
          uint32_t b4[4];
          ldsm_x4(b4, boff[p] + ks*32);
          MMA16816(c2[2*p],   a4, b4[0], b4[1]);
          MMA16816(c2[2*p+1], a4, b4[2], b4[3]);
        }
      }
    }
  }

  // epilogue: write xc to g_y[:, 90:180]
  {
    int r1 = w*16 + (lane>>2);
#pragma unroll
    for (int half=0; half<2; half++){
      int l = r1 + half*8;
      size_t pix = pix0 + (size_t)(l>>4)*IMG + (l&15);
      float* ydst = g_y + pix*180 + 90;
#pragma unroll
      for (int nt=0;nt<12;nt++){
        int n0 = nt*8 + (lane&3)*2;
        if (n0 < 90)
          *(float2*)(ydst + n0) = make_float2(c2[nt][half*2], c2[nt][half*2+1]);
      }
    }
  }
}

// =============== T3: t_proj ===============
__global__ void __launch_bounds__(256,2) t_proj(const float* __restrict__ x,
                                                const float* __restrict__ pb,
                                                const float* __restrict__ nw,
                                                float* __restrict__ out){
  extern __shared__ __align__(16) char smc[];
  __shared__ float scl[64];
  __nv_bfloat16* Ab = (__nv_bfloat16*)smc;
  const uint32_t O_B0 = 6*4608*2, O_B1 = O_B0 + 13824*2;
  uint32_t sbase = (uint32_t)__cvta_generic_to_shared(smc);
  int tid = threadIdx.x; int lane = tid&31, wid = tid>>5;
  int wm = wid&1, wn = wid>>1;
  int r0 = blockIdx.x*64; int bb = r0>>16; int p0 = r0&65535;

  for (int t=tid; t<1728; t+=256)
    cpa16(sbase + O_B0 + t*16, (const char*)(g_pk_pj) + t*16);
  CP_COMMIT();

  for (int idx=tid; idx<64*192; idx+=256){
    int px = idx/192, cc = idx - px*192;
    float v = (cc<180) ? g_y[(size_t)(r0+px)*180 + cc] : 0.f;
    __nv_bfloat16 h,l; cvhl(v,h,l);
    int t = cc>>6, k = cc&63;
    Ab[t*4608 + px*72 + k]     = h;
    Ab[(t+3)*4608 + px*72 + k] = l;
  }
  float c[2][6][4];
#pragma unroll
  for (int mt=0;mt<2;mt++)
#pragma unroll
    for (int nt=0;nt<6;nt++)
#pragma unroll
      for (int e=0;e<4;e++) c[mt][nt][e]=0.f;

  for (int i=0;i<6;i++){
    uint32_t bo = (i&1) ? O_B1 : O_B0;
    if (i<5){
      uint32_t bn = ((i+1)&1) ? O_B1 : O_B0;
      for (int t=tid; t<1728; t+=256)
        cpa16(sbase + bn + t*16, (const char*)(g_pk_pj + (i+1)*13824) + t*16);
      CP_COMMIT();
      CP_WAIT(1);
    } else {
      CP_WAIT(0);
    }
    __syncthreads();
    if (i<3){
      mma_pass<72,72,4>(sbase + (uint32_t)(i*4608*2),     sbase + bo, c, lane, wm, wn);
      mma_pass<72,72,4>(sbase + (uint32_t)((3+i)*4608*2), sbase + bo, c, lane, wm, wn);
    } else {
      mma_pass<72,72,4>(sbase + (uint32_t)((i-3)*4608*2), sbase + bo, c, lane, wm, wn);
    }
    __syncthreads();
  }
  float* stash = (float*)smc;
#pragma unroll
  for (int mt=0;mt<2;mt++){
    int r1 = wm*32 + mt*16 + (lane>>2);
#pragma unroll
    for (int nt=0;nt<6;nt++){
      int n0 = wn*48 + nt*8 + (lane&3)*2;
      if (n0 < 180){
        float b0=__ldg(pb+n0), b1=__ldg(pb+n0+1);
        stash[r1*181+n0]       = c[mt][nt][0]+b0;
        stash[r1*181+n0+1]     = c[mt][nt][1]+b1;
        stash[(r1+8)*181+n0]   = c[mt][nt][2]+b0;
        stash[(r1+8)*181+n0+1] = c[mt][nt][3]+b1;
      }
    }
  }
  __syncthreads();
  if (tid < 64){
    const float* row = stash + tid*181;
    float s = 0.f;
    for (int cc=0; cc<180; cc++){ float v = row[cc]; s += v*v; }
    scl[tid] = rsqrtf(s*(1.f/180.f) + 1.1920929e-07f);
  }
  __syncthreads();
  {
    int px = tid&63;
    int q = tid>>6;
    float sc = scl[px];
    for (int ci=q; ci<180; ci+=4){
      size_t a = ((size_t)(bb*180+ci))*NPIX + p0 + px;
      out[a] = x[a] + stash[px*181+ci]*sc*__ldg(nw+ci);
    }
  }
}

// =============== launch ===============
extern "C" void kernel_launch(void* const* d_in, const int* in_sizes, int n_in,
                              void* d_out, int out_size){
  const float* x     = (const float*)d_in[0];
  const float* w1    = (const float*)d_in[1];
  const float* b1    = (const float*)d_in[2];
  const float* w2    = (const float*)d_in[3];
  const float* b2    = (const float*)d_in[4];
  const float* w3    = (const float*)d_in[5];
  const float* b3    = (const float*)d_in[6];
  const float* lw    = (const float*)d_in[7];
  const float* lb    = (const float*)d_in[8];
  const float* sl_w  = (const float*)d_in[9];
  const float* sl_b  = (const float*)d_in[10];
  const float* ppw   = (const float*)d_in[11];
  const float* ppb   = (const float*)d_in[12];
  const float* ln1w  = (const float*)d_in[13];
  const float* ln1b  = (const float*)d_in[14];
  const float* l1w   = (const float*)d_in[15];
  const float* l1b   = (const float*)d_in[16];
  const float* ln2w  = (const float*)d_in[17];
  const float* ln2b  = (const float*)d_in[18];
  const float* l2w   = (const float*)d_in[19];
  const float* l2b   = (const float*)d_in[20];
  const float* ln3w  = (const float*)d_in[21];
  const float* ln3b  = (const float*)d_in[22];
  const float* l3w   = (const float*)d_in[23];
  const float* l3b   = (const float*)d_in[24];
  const float* pjw   = (const float*)d_in[25];
  const float* pjb   = (const float*)d_in[26];
  const float* nrmw  = (const float*)d_in[27];
  float* out = (float*)d_out;

  const int SM_M2  = 6*4608*2 + 2*13824*2;       // 110592 B
  const int SM_TH  = 7168*2*2 + 2*10752*2;       // 71680 B
  const int SM_CH  = 4*50688;                    // 202752 B
  cudaFuncSetAttribute(mega2,   cudaFuncAttributeMaxDynamicSharedMemorySize, SM_M2);
  cudaFuncSetAttribute(t_h3,    cudaFuncAttributeMaxDynamicSharedMemorySize, SM_TH);
  cudaFuncSetAttribute(attn_ch, cudaFuncAttributeMaxDynamicSharedMemorySize, SM_CH);
  cudaFuncSetAttribute(t_proj,  cudaFuncAttributeMaxDynamicSharedMemorySize, SM_M2);

  mega1<<<1760,256>>>(x, w1, b1, lw, pjw, w3,
                      ppw, ppb, ln1w, ln1b, l1w, l1b, ln2w, ln2b, l2w, l2b,
                      ln3w, ln3b, l3w, l3b);
  mega2<<<5504,256,SM_M2>>>(x, lb, w2, b2);
  t_h3<<<TOTPIX/64,256,SM_TH>>>(b3);
  attn_sp<<<NWIN,256>>>(sl_w, sl_b);            // launch #4 -> profiled
  attn_ch<<<NWIN,512,SM_CH>>>();
  t_proj<<<TOTPIX/64,256,SM_M2>>>(x, pjb, nrmw, out);
}

// round 11
// speedup vs baseline: 1.1511x; 1.1511x over previous
#include <cuda_runtime.h>
#include <cuda_bf16.h>
#include <math.h>
#include <stdint.h>

#define NBATCH 4
#define NCH    180
#define IMG    256
#define NPIX   (IMG*IMG)            // 65536
#define TOTPIX (NBATCH*NPIX)        // 262144
#define MIDC   36
#define NWIN   1024

// ---- scratch (device globals; no allocation allowed) ----
__device__ float g_h1[(size_t)TOTPIX*MIDC];
__device__ float g_h2[(size_t)TOTPIX*MIDC];
__device__ float g_qv[(size_t)TOTPIX*NCH];
__device__ float g_y [(size_t)TOTPIX*NCH];
__device__ float g_pos[961*6];
__device__ float g_rpb[6*256*64];
__device__ __align__(16) __nv_bfloat16 g_pk_lw[6*13824];
__device__ __align__(16) __nv_bfloat16 g_pk_pj[6*13824];
__device__ __align__(16) __nv_bfloat16 g_pk_w3[2*10752];

typedef unsigned long long u64;

__device__ __forceinline__ u64 pk2(float lo, float hi){
  u64 r; asm("mov.b64 %0,{%1,%2};" : "=l"(r) : "f"(lo), "f"(hi)); return r;
}
__device__ __forceinline__ u64 dup2(float v){ return pk2(v, v); }
__device__ __forceinline__ void up2(u64 v, float& lo, float& hi){
  asm("mov.b64 {%0,%1},%2;" : "=f"(lo), "=f"(hi) : "l"(v));
}
__device__ __forceinline__ u64 ffma2(u64 a, u64 b, u64 c){
  u64 d; asm("fma.rn.f32x2 %0,%1,%2,%3;" : "=l"(d) : "l"(a), "l"(b), "l"(c)); return d;
}
__device__ __forceinline__ u64 fmul2(u64 a, u64 b){
  u64 d; asm("mul.rn.f32x2 %0,%1,%2;" : "=l"(d) : "l"(a), "l"(b)); return d;
}
__device__ __forceinline__ float lrelu(float v){ return v >= 0.f ? v : 0.2f*v; }

__device__ __forceinline__ void cvhl(float v, __nv_bfloat16& h, __nv_bfloat16& l){
  h = __float2bfloat16(v);
  l = __float2bfloat16(v - __bfloat162float(h));
}

// ---- portable tensor-core primitives ----
#define MMA16816(c, a, b0, b1) \
  asm volatile("mma.sync.aligned.m16n8k16.row.col.f32.bf16.bf16.f32 " \
    "{%0,%1,%2,%3}, {%4,%5,%6,%7}, {%8,%9}, {%0,%1,%2,%3};" \
    : "+f"((c)[0]), "+f"((c)[1]), "+f"((c)[2]), "+f"((c)[3]) \
    : "r"((a)[0]), "r"((a)[1]), "r"((a)[2]), "r"((a)[3]), "r"(b0), "r"(b1))

__device__ __forceinline__ void ldsm_x4(uint32_t r[4], uint32_t saddr){
  asm volatile("ldmatrix.sync.aligned.m8n8.x4.shared.b16 {%0,%1,%2,%3}, [%4];"
    : "=r"(r[0]),"=r"(r[1]),"=r"(r[2]),"=r"(r[3]) : "r"(saddr));
}
__device__ __forceinline__ void ldsm_x4_t(uint32_t r[4], uint32_t saddr){
  asm volatile("ldmatrix.sync.aligned.m8n8.x4.trans.shared.b16 {%0,%1,%2,%3}, [%4];"
    : "=r"(r[0]),"=r"(r[1]),"=r"(r[2]),"=r"(r[3]) : "r"(saddr));
}
__device__ __forceinline__ void cpa16(uint32_t d, const void* s){
  asm volatile("cp.async.cg.shared.global [%0], [%1], 16;" :: "r"(d), "l"(s));
}
#define CP_COMMIT() asm volatile("cp.async.commit_group;" ::: "memory")
#define CP_WAIT(n)  asm volatile("cp.async.wait_group %0;" :: "n"(n) : "memory")

template<int SA, int SB, int NKS>
__device__ __forceinline__ void mma_pass(uint32_t aBase, uint32_t bBase,
                                         float c[2][6][4], int lane, int wm, int wn){
  uint32_t aoff[2], boff[3];
  int ar = (lane&7) + ((lane&8)?8:0);
  int ak = (lane&16)?8:0;
#pragma unroll
  for (int mt=0;mt<2;mt++) aoff[mt] = aBase + (uint32_t)(((wm*32+mt*16+ar)*SA + ak)*2);
  int br = (lane&7) + ((lane&16)?8:0);
  int bk = (lane&8)?8:0;
#pragma unroll
  for (int p=0;p<3;p++) boff[p] = bBase + (uint32_t)(((wn*48+p*16+br)*SB + bk)*2);

  uint32_t a[2][2][4], b[2][3][4];
  ldsm_x4(a[0][0], aoff[0]);
  ldsm_x4(a[0][1], aoff[1]);
#pragma unroll
  for (int p=0;p<3;p++) ldsm_x4(b[0][p], boff[p]);
#pragma unroll
  for (int ks=0;ks<NKS;ks++){
    int cur = ks&1, nxt = cur^1;
    if (ks+1 < NKS){
      ldsm_x4(a[nxt][0], aoff[0] + (ks+1)*32);
      ldsm_x4(a[nxt][1], aoff[1] + (ks+1)*32);
#pragma unroll
      for (int p=0;p<3;p++) ldsm_x4(b[nxt][p], boff[p] + (ks+1)*32);
    }
#pragma unroll
    for (int p=0;p<3;p++){
      MMA16816(c[0][2*p],   a[cur][0], b[cur][p][0], b[cur][p][1]);
      MMA16816(c[1][2*p],   a[cur][1], b[cur][p][0], b[cur][p][1]);
      MMA16816(c[0][2*p+1], a[cur][0], b[cur][p][2], b[cur][p][3]);
      MMA16816(c[1][2*p+1], a[cur][1], b[cur][p][2], b[cur][p][3]);
    }
  }
}

__device__ __forceinline__ void ln_relu11(const float* in, const float* w, const float* b, float* out){
  float m = 0.f;
#pragma unroll
  for (int j=0;j<11;j++) m += in[j];
  m *= (1.f/11.f);
  float var = 0.f;
#pragma unroll
  for (int j=0;j<11;j++){ float d = in[j]-m; var += d*d; }
  var *= (1.f/11.f);
  float inv = rsqrtf(var + 1e-5f);
#pragma unroll
  for (int j=0;j<11;j++) out[j] = fmaxf((in[j]-m)*inv*w[j] + b[j], 0.f);
}

// =============== MEGA1 ===============
__global__ void __launch_bounds__(256) mega1(
    const float* __restrict__ x,  const float* __restrict__ w1, const float* __restrict__ b1,
    const float* __restrict__ lw, const float* __restrict__ pjw, const float* __restrict__ w3,
    const float* __restrict__ pw, const float* __restrict__ pb,
    const float* __restrict__ ln1w, const float* __restrict__ ln1b,
    const float* __restrict__ p1w,  const float* __restrict__ p1b,
    const float* __restrict__ ln2w, const float* __restrict__ ln2b,
    const float* __restrict__ p2w,  const float* __restrict__ p2b,
    const float* __restrict__ ln3w, const float* __restrict__ ln3b,
    const float* __restrict__ p3w,  const float* __restrict__ p3b){
  __shared__ __align__(16) float ws[180*36];
  int gid = blockIdx.x;
  int tid = threadIdx.x;

  if (gid < 1024){
    for (int t=tid;t<180*36;t+=256) ws[t]=w1[t];
    __syncthreads();
    int r = gid*256 + tid;
    int b = r>>16; int p = r&65535;
    const float* xp = x + (size_t)b*NCH*NPIX + p;
    u64 acc2[18];
#pragma unroll
    for (int q=0;q<18;q++) acc2[q] = pk2(b1[2*q], b1[2*q+1]);
    for (int ci=0;ci<180;ci++){
      u64 v2 = dup2(xp[(size_t)ci*NPIX]);
      const ulonglong2* wr = (const ulonglong2*)(ws + ci*36);
#pragma unroll
      for (int q=0;q<9;q++){
        ulonglong2 w = wr[q];
        acc2[2*q]   = ffma2(v2, w.x, acc2[2*q]);
        acc2[2*q+1] = ffma2(v2, w.y, acc2[2*q+1]);
      }
    }
    float2* dst = (float2*)(g_h1 + (size_t)r*36);
#pragma unroll
    for (int q=0;q<18;q++){
      float lo,hi; up2(acc2[q], lo, hi);
      dst[q] = make_float2(lrelu(lo), lrelu(hi));
    }
  } else if (gid < 1672){
    int which = (gid >= 1348);
    const float* W = which ? pjw : lw;
    __nv_bfloat16* dst = which ? g_pk_pj : g_pk_lw;
    int base = which ? 1348 : 1024;
    int idx = (gid-base)*256 + tid;
    if (idx < 6*13824){
      int cc = idx/13824, r = idx - cc*13824, n = r/72, k = r - n*72;
      int half = cc/3, kc = cc - half*3;
      int kk = kc*64 + k;
      float v = (n<180 && k<64 && kk<180) ? W[kk*180+n] : 0.f;
      __nv_bfloat16 h, l; cvhl(v, h, l);
      dst[idx] = half ? l : h;
    }
  } else if (gid < 1756){
    int idx = (gid-1672)*256 + tid;
    if (idx < 2*10752){
      int cc = idx/10752, r = idx - cc*10752, n = r/56, k = r - n*56;
      float v = (n<180 && k<36) ? w3[k*180+n] : 0.f;
      __nv_bfloat16 h, l; cvhl(v, h, l);
      g_pk_w3[idx] = cc ? l : h;
    }
  } else {
    int n = (gid-1756)*256 + tid;
    if (n < 961){
      float i0 = (float)(n/31) - 15.f;
      float i1 = (float)(n%31) - 15.f;
      float p[11], t[11];
#pragma unroll
      for (int j=0;j<11;j++) p[j] = i0*pw[j] + i1*pw[11+j] + pb[j];
      ln_relu11(p, ln1w, ln1b, t);
#pragma unroll
      for (int k=0;k<11;k++){ float s=p1b[k];
#pragma unroll
        for (int j=0;j<11;j++) s += t[j]*p1w[j*11+k]; p[k]=s; }
      ln_relu11(p, ln2w, ln2b, t);
#pragma unroll
      for (int k=0;k<11;k++){ float s=p2b[k];
#pragma unroll
        for (int j=0;j<11;j++) s += t[j]*p2w[j*11+k]; p[k]=s; }
      ln_relu11(p, ln3w, ln3b, t);
#pragma unroll
      for (int k=0;k<6;k++){ float s=p3b[k];
#pragma unroll
        for (int j=0;j<11;j++) s += t[j]*p3w[j*6+k];
        g_pos[n*6+k] = s; }
    }
  }
}

// =============== MEGA2: t_lin + conv3 + rpb ===============
__global__ void __launch_bounds__(256,2) mega2(const float* __restrict__ x,
                                               const float* __restrict__ lb,
                                               const float* __restrict__ w2,
                                               const float* __restrict__ b2){
  extern __shared__ __align__(16) char smc[];
  int gid = blockIdx.x;
  int tid = threadIdx.x;

  if (gid < 4096){
    __nv_bfloat16* Ab = (__nv_bfloat16*)smc;
    const uint32_t O_B0 = 6*4608*2, O_B1 = O_B0 + 13824*2;
    uint32_t sbase = (uint32_t)__cvta_generic_to_shared(smc);
    int lane = tid&31, wid = tid>>5;
    int wm = wid&1, wn = wid>>1;
    int r0 = gid*64; int bb = r0>>16; int p0 = r0&65535;

    for (int t=tid; t<1728; t+=256)
      cpa16(sbase + O_B0 + t*16, (const char*)(g_pk_lw) + t*16);
    CP_COMMIT();

    for (int idx=tid; idx<192*64; idx+=256){
      int c = idx>>6, px = idx&63;
      float v = (c<180) ? x[((size_t)(bb*180+c))*NPIX + p0+px] : 0.f;
      __nv_bfloat16 h,l; cvhl(v,h,l);
      int t = c>>6, k = c&63;
      Ab[t*4608 + px*72 + k]     = h;
      Ab[(t+3)*4608 + px*72 + k] = l;
    }
    float c[2][6][4];
#pragma unroll
    for (int mt=0;mt<2;mt++)
#pragma unroll
      for (int nt=0;nt<6;nt++)
#pragma unroll
        for (int e=0;e<4;e++) c[mt][nt][e]=0.f;

    for (int i=0;i<6;i++){
      uint32_t bo = (i&1) ? O_B1 : O_B0;
      if (i<5){
        uint32_t bn = ((i+1)&1) ? O_B1 : O_B0;
        for (int t=tid; t<1728; t+=256)
          cpa16(sbase + bn + t*16, (const char*)(g_pk_lw + (i+1)*13824) + t*16);
        CP_COMMIT();
        CP_WAIT(1);
      } else {
        CP_WAIT(0);
      }
      __syncthreads();
      if (i<3){
        mma_pass<72,72,4>(sbase + (uint32_t)(i*4608*2),     sbase + bo, c, lane, wm, wn);
        mma_pass<72,72,4>(sbase + (uint32_t)((3+i)*4608*2), sbase + bo, c, lane, wm, wn);
      } else {
        mma_pass<72,72,4>(sbase + (uint32_t)((i-3)*4608*2), sbase + bo, c, lane, wm, wn);
      }
      __syncthreads();
    }
    float* stash = (float*)smc;
#pragma unroll
    for (int mt=0;mt<2;mt++){
      int r1 = wm*32 + mt*16 + (lane>>2);
#pragma unroll
      for (int nt=0;nt<6;nt++){
        int n0 = wn*48 + nt*8 + (lane&3)*2;
        if (n0 < 180){
          float bl0=__ldg(lb+n0), bl1=__ldg(lb+n0+1);
          stash[r1*181+n0]       = c[mt][nt][0]+bl0;
          stash[r1*181+n0+1]     = c[mt][nt][1]+bl1;
          stash[(r1+8)*181+n0]   = c[mt][nt][2]+bl0;
          stash[(r1+8)*181+n0+1] = c[mt][nt][3]+bl1;
        }
      }
    }
    __syncthreads();
    int f = tid;
    int px = f/180, co = f - px*180;
    for (; f < 64*180; f += 256){
      g_y[(size_t)r0*180 + f] = stash[px*181+co];
      co += 256; if (co >= 180){ co -= 180; px++; if (co >= 180){ co -= 180; px++; } }
    }
  } else if (gid < 5120){
    float* ins = (float*)smc;
    float* wsh = (float*)smc + 11988;
    int cg = gid - 4096;
    int b = cg>>8; int hy0 = ((cg>>4)&15)*16, wx0 = (cg&15)*16;
    for (int t=tid;t<18*18*36;t+=256){
      int ci = t%36; int rc = t/36; int col = rc%18; int row = rc/18;
      int gh = hy0+row-1, gw = wx0+col-1;
      float v = 0.f;
      if (gh>=0 && gh<IMG && gw>=0 && gw<IMG)
        v = g_h1[((size_t)(b*IMG+gh)*IMG+gw)*36 + ci];
      ins[(row*18+col)*37+ci] = v;
    }
    for (int t=tid;t<9*36*36;t+=256) wsh[t] = w2[t];
    __syncthreads();
    int tx = tid&15, ty = tid>>4;
    float acc[36];
#pragma unroll
    for (int co=0;co<36;co++) acc[co] = b2[co];
    for (int dy=0;dy<3;dy++)
      for (int dx=0;dx<3;dx++){
        const float* wp = wsh + (dy*3+dx)*36*36;
        const float* ip = ins + ((ty+dy)*18 + tx+dx)*37;
        for (int ci=0;ci<36;ci++){
          float v = ip[ci];
          const float* wr = wp + ci*36;
#pragma unroll
          for (int co=0;co<36;co++) acc[co] += v*wr[co];
        }
      }
    size_t o = ((size_t)(b*IMG+hy0+ty)*IMG + wx0+tx)*36;
    float4* dst = (float4*)(g_h2 + o);
#pragma unroll
    for (int q=0;q<9;q++){
      float4 r; r.x=lrelu(acc[q*4]); r.y=lrelu(acc[q*4+1]); r.z=lrelu(acc[q*4+2]); r.w=lrelu(acc[q*4+3]);
      dst[q]=r;
    }
  } else {
    int idx = (gid-5120)*256 + tid;
    if (idx < 6*256*64){
      int nh = idx/16384;
      int r  = idx - nh*16384;
      int l  = r>>6;
      int m  = r&63;
      int rl = l>>4, cl = l&15;
      int mh = m>>3, mw = m&7;
      float s = 0.f;
#pragma unroll
      for (int rh=0;rh<2;rh++)
#pragma unroll
        for (int rw=0;rw<2;rw++){
          int r2 = mh*2+rh, c2 = mw*2+rw;
          int k = (rl-r2+15)*31 + (cl-c2+15);
          s += g_pos[k*6+nh];
        }
      g_rpb[idx] = 0.25f*s;
    }
  }
}

// =============== T2: t_h3 ===============
__global__ void __launch_bounds__(256,2) t_h3(const float* __restrict__ b3){
  extern __shared__ __align__(16) char smc[];
  __nv_bfloat16* Ab = (__nv_bfloat16*)smc;
  const uint32_t O_B = 7168*2;
  uint32_t sbase = (uint32_t)__cvta_generic_to_shared(smc);
  int tid = threadIdx.x; int lane = tid&31, wid = tid>>5;
  int wm = wid&1, wn = wid>>1;
  int r0 = blockIdx.x*64;

  for (int t=tid; t<2688; t+=256)
    cpa16(sbase + O_B + t*16, (const char*)(g_pk_w3) + t*16);
  CP_COMMIT();

  for (int idx=tid; idx<64*48; idx+=256){
    int px = idx/48, cc = idx - px*48;
    float v = (cc<36) ? g_h2[(size_t)(r0+px)*36 + cc] : 0.f;
    __nv_bfloat16 h,l; cvhl(v,h,l);
    Ab[px*56 + cc]        = h;
    Ab[3584 + px*56 + cc] = l;
  }
  CP_WAIT(0);
  __syncthreads();
  float c[2][6][4];
#pragma unroll
  for (int mt=0;mt<2;mt++)
#pragma unroll
    for (int nt=0;nt<6;nt++)
#pragma unroll
      for (int e=0;e<4;e++) c[mt][nt][e]=0.f;

  mma_pass<56,56,3>(sbase,           sbase + O_B,           c, lane, wm, wn);
  mma_pass<56,56,3>(sbase + 3584*2,  sbase + O_B,           c, lane, wm, wn);
  mma_pass<56,56,3>(sbase,           sbase + O_B + 10752*2, c, lane, wm, wn);
  __syncthreads();
  float* stash = (float*)smc;
#pragma unroll
  for (int mt=0;mt<2;mt++){
    int r1 = wm*32 + mt*16 + (lane>>2);
#pragma unroll
    for (int nt=0;nt<6;nt++){
      int n0 = wn*48 + nt*8 + (lane&3)*2;
      if (n0 < 180){
        float b30=__ldg(b3+n0), b31=__ldg(b3+n0+1);
        stash[r1*181+n0]       = c[mt][nt][0]+b30;
        stash[r1*181+n0+1]     = c[mt][nt][1]+b31;
        stash[(r1+8)*181+n0]   = c[mt][nt][2]+b30;
        stash[(r1+8)*181+n0+1] = c[mt][nt][3]+b31;
      }
    }
  }
  __syncthreads();
  {
    int f = tid;
    int px = f/180, co = f - px*180;
    for (; f < 64*180; f += 256){
      g_qv[(size_t)r0*180 + f] = stash[px*181+co] * g_y[(size_t)r0*180 + f];
      co += 256; if (co >= 180){ co -= 180; px++; if (co >= 180){ co -= 180; px++; } }
    }
  }
}

// =============== attn_ch: channel attention via mma, pixel-major + trans-LDSM ===============
// smem (bf16 elems): QH=0 QL=26624 VH=53248 VL=79872 (each [256][104]); total 212992 B
// cmap (after phase1): CMH=0 CML=9984 (each [96][104]) overwrites Q region
__global__ void __launch_bounds__(512) attn_ch(){
  extern __shared__ __align__(16) char smc[];
  uint32_t sbase = (uint32_t)__cvta_generic_to_shared(smc);
  __nv_bfloat16* sm16 = (__nv_bfloat16*)smc;
  int tid = threadIdx.x; int lane = tid&31; int w = tid>>5;
  int bw = blockIdx.x;
  int b = bw>>8, wy = (bw>>4)&15, wx = bw&15;
  size_t pix0 = ((size_t)(b*IMG + wy*16))*IMG + wx*16;

  const int QH=0, QL=26624, VH=53248, VL=79872;
  // ---- load g_qv once, pixel-major hi/lo; pad columns zeroed inline ----
  // zero pad cols (90..103 for Q; 90..103 for V) first via full-row writes below:
  for (int t=tid; t<256*14; t+=512){
    int px = t/14, c = 90 + t%14;
    sm16[QH + px*104 + c] = __nv_bfloat16(0.f);
    sm16[QL + px*104 + c] = __nv_bfloat16(0.f);
    sm16[VH + px*104 + c] = __nv_bfloat16(0.f);
    sm16[VL + px*104 + c] = __nv_bfloat16(0.f);
  }
  for (int idx=tid; idx<256*45; idx+=512){
    int px = idx/45, q4 = idx - px*45;
    size_t pix = pix0 + (size_t)(px>>4)*IMG + (px&15);
    float4 v4 = *(const float4*)(g_qv + pix*180 + q4*4);
    float vals[4] = {v4.x, v4.y, v4.z, v4.w};
#pragma unroll
    for (int e=0;e<4;e++){
      int c = q4*4 + e;
      __nv_bfloat16 h,l; cvhl(vals[e], h, l);
      if (c < 90){
        sm16[QH + px*104 + c] = h;
        sm16[QL + px*104 + c] = l;
      } else {
        sm16[VH + px*104 + (c-90)] = h;
        sm16[VL + px*104 + (c-90)] = l;
      }
    }
  }
  __syncthreads();

  // ---- phase1: cmap[c][d] = sum_l Q[l][c] V[l][d]  (trans-LDSM both operands) ----
  float c1[6][4];
#pragma unroll
  for (int nt=0;nt<6;nt++)
#pragma unroll
    for (int e=0;e<4;e++) c1[nt][e]=0.f;
  if (w < 12){
    int wm = w % 6, wn = w / 6;       // c-tile 16, d-tile 48
    // A-trans address pattern: row(l) uses (lane&7)+((lane&16)?8:0), col(c) += (lane&8)?8:0
    int arT = (lane&7) + ((lane&16)?8:0);
    int akT = (lane&8)?8:0;
    // B-trans: row(l) uses (lane&7)+((lane&8)?8:0), col(d) += (lane&16)?8:0
    int brT = (lane&7) + ((lane&8)?8:0);
    int bkT = (lane&16)?8:0;
    const int passes[3][2] = {{QH,VH},{QL,VH},{QH,VL}};
#pragma unroll
    for (int ps=0; ps<3; ps++){
      uint32_t aoff = sbase + (uint32_t)((passes[ps][0] + arT*104 + wm*16 + akT)*2);
      uint32_t boff[3];
#pragma unroll
      for (int p=0;p<3;p++)
        boff[p] = sbase + (uint32_t)((passes[ps][1] + brT*104 + wn*48 + p*16 + bkT)*2);
      for (int ks=0;ks<16;ks++){          // k = pixels, 16 per chunk
        uint32_t a4[4];
        ldsm_x4_t(a4, aoff + ks*16*208);  // 16 rows * 104 elems * 2B
#pragma unroll
        for (int p=0;p<3;p++){
          uint32_t b4[4];
          ldsm_x4_t(b4, boff[p] + ks*16*208);
          MMA16816(c1[2*p],   a4, b4[0], b4[1]);
          MMA16816(c1[2*p+1], a4, b4[2], b4[3]);
        }
      }
    }
  }
  __syncthreads();   // Q region dead -> becomes cmap

  const int CMH=0, CML=9984;
  // zero cmap region (2*9984 elems = 39936 B) with uint4
  {
    uint4* z = (uint4*)smc;
    for (int t=tid; t<2496; t+=512) z[t] = make_uint4(0,0,0,0);
  }
  __syncthreads();
  if (w < 12){
    int wm = w % 6, wn = w / 6;
    int c0 = wm*16 + (lane>>2);
#pragma unroll
    for (int nt=0;nt<6;nt++){
      int d0 = wn*48 + nt*8 + (lane&3)*2;
      if (d0 < 90){
#pragma unroll
        for (int half=0; half<2; half++){
          int cc = c0 + half*8;
          if (cc < 90){
            float v0 = c1[nt][half*2]   * (1.f/256.f);
            float v1 = c1[nt][half*2+1] * (1.f/256.f);
            __nv_bfloat16 h0,l0,h1,l1; cvhl(v0,h0,l0); cvhl(v1,h1,l1);
            sm16[CMH + cc*104 + d0]   = h0;
            sm16[CMH + cc*104 + d0+1] = h1;
            sm16[CML + cc*104 + d0]   = l0;
            sm16[CML + cc*104 + d0+1] = l1;
          }
        }
      }
    }
  }
  __syncthreads();

  // ---- phase2: xc[l][c] = sum_d V[l][d] * cmap[c][d]  (non-trans) ----
  float c2[12][4];
#pragma unroll
  for (int nt=0;nt<12;nt++)
#pragma unroll
    for (int e=0;e<4;e++) c2[nt][e]=0.f;
  {
    int ar = (lane&7) + ((lane&8)?8:0);
    int ak = (lane&16)?8:0;
    int br = (lane&7) + ((lane&16)?8:0);
    int bk = (lane&8)?8:0;
    const int passes[3][2] = {{VH,CMH},{VL,CMH},{VH,CML}};
#pragma unroll
    for (int ps=0; ps<3; ps++){
      uint32_t aoff = sbase + (uint32_t)((passes[ps][0] + (w*16+ar)*104 + ak)*2);
      uint32_t boff[6];
#pragma unroll
      for (int p=0;p<6;p++)
        boff[p] = sbase + (uint32_t)((passes[ps][1] + (p*16+br)*104 + bk)*2);
      for (int ks=0;ks<6;ks++){
        uint32_t a4[4];
        ldsm_x4(a4, aoff + ks*32);
#pragma unroll
        for (int p=0;p<6;p++){
          uint32_t b4[4];
          ldsm_x4(b4, boff[p] + ks*32);
          MMA16816(c2[2*p],   a4, b4[0], b4[1]);
          MMA16816(c2[2*p+1], a4, b4[2], b4[3]);
        }
      }
    }
  }

  // epilogue: write xc to g_y[:, 90:180]
  {
    int r1 = w*16 + (lane>>2);
#pragma unroll
    for (int half=0; half<2; half++){
      int l = r1 + half*8;
      size_t pix = pix0 + (size_t)(l>>4)*IMG + (l&15);
      float* ydst = g_y + pix*180 + 90;
#pragma unroll
      for (int nt=0;nt<12;nt++){
        int n0 = nt*8 + (lane&3)*2;
        if (n0 < 90)
          *(float2*)(ydst + n0) = make_float2(c2[nt][half*2], c2[nt][half*2+1]);
      }
    }
  }
}

// =============== attn_sp: spatial attention (vp-only smem) ===============
__global__ void __launch_bounds__(256,3) attn_sp(const float* __restrict__ sl_w,
                                                 const float* __restrict__ sl_b){
  __shared__ float vp[6144];
  int tid = threadIdx.x;
  int l = tid;
  int bw = blockIdx.x;
  int b = bw>>8, wy = (bw>>4)&15, wx = bw&15;
  size_t pix0 = ((size_t)(b*IMG + wy*16))*IMG + wx*16;
  size_t pix  = pix0 + (size_t)(l>>4)*IMG + (l&15);

  float slw0=__ldg(sl_w), slw1=__ldg(sl_w+1), slw2=__ldg(sl_w+2), slw3=__ldg(sl_w+3), slb=__ldg(sl_b);
  for (int idx=tid; idx<6144; idx+=256){
    int nh = idx>>10; int r = idx & 1023; int m = r>>4; int hd = r&15;
    float val = 0.f;
    if (hd < 15){
      int mh = m>>3, mw = m&7; int ch = 90 + nh*15 + hd;
      size_t pA = pix0 + (size_t)(mh*2)*IMG + mw*2;
      val = slb + slw0*__ldg(g_qv + pA*180 + ch)
                + slw1*__ldg(g_qv + (pA+1)*180 + ch)
                + slw2*__ldg(g_qv + (pA+IMG)*180 + ch)
                + slw3*__ldg(g_qv + (pA+IMG+1)*180 + ch);
    }
    vp[idx] = val;
  }
  __syncthreads();

  float* ydst = g_y + pix*180;
  const float* qrow = g_qv + pix*180;
  for (int nh=0; nh<6; nh++){
    float qs[15];
#pragma unroll
    for (int hd=0;hd<15;hd++) qs[hd] = __ldg(qrow + nh*15 + hd);
    u64 q2[8];
#pragma unroll
    for (int p=0;p<7;p++) q2[p] = pk2(qs[2*p], qs[2*p+1]);
    q2[7] = pk2(qs[14], 0.f);
    const float* vph = vp + (nh<<10);
    const float* rpbrow = g_rpb + ((size_t)((nh<<8) + l))*64;
    u64 xs2[8];
#pragma unroll
    for (int p=0;p<8;p++) xs2[p]=0ull;
    for (int m0=0;m0<64;m0+=4){
      float4 rb = *(const float4*)(rpbrow + m0);
      float rbv[4] = {rb.x, rb.y, rb.z, rb.w};
#pragma unroll
      for (int t=0;t<4;t++){
        const ulonglong2* vpp = (const ulonglong2*)(vph + ((m0+t)<<4));
        ulonglong2 wA = vpp[0], wB = vpp[1], wC = vpp[2], wD = vpp[3];
        u64 d2 = fmul2(q2[0], wA.x);
        d2 = ffma2(q2[1], wA.y, d2);
        d2 = ffma2(q2[2], wB.x, d2);
        d2 = ffma2(q2[3], wB.y, d2);
        d2 = ffma2(q2[4], wC.x, d2);
        d2 = ffma2(q2[5], wC.y, d2);
        d2 = ffma2(q2[6], wD.x, d2);
        d2 = ffma2(q2[7], wD.y, d2);
        float lo,hi; up2(d2, lo, hi);
        u64 s2 = dup2((lo+hi)*(1.f/15.f) + rbv[t]);
        xs2[0] = ffma2(s2, wA.x, xs2[0]);
        xs2[1] = ffma2(s2, wA.y, xs2[1]);
        xs2[2] = ffma2(s2, wB.x, xs2[2]);
        xs2[3] = ffma2(s2, wB.y, xs2[3]);
        xs2[4] = ffma2(s2, wC.x, xs2[4]);
        xs2[5] = ffma2(s2, wC.y, xs2[5]);
        xs2[6] = ffma2(s2, wD.x, xs2[6]);
        xs2[7] = ffma2(s2, wD.y, xs2[7]);
      }
    }
#pragma unroll
    for (int p=0;p<7;p++){
      float lo,hi; up2(xs2[p], lo, hi);
      ydst[nh*15+2*p] = lo; ydst[nh*15+2*p+1] = hi;
    }
    { float lo,hi; up2(xs2[7], lo, hi); ydst[nh*15+14] = lo; }
  }
}

// =============== T3: t_proj ===============
__global__ void __launch_bounds__(256,2) t_proj(const float* __restrict__ x,
                                                const float* __restrict__ pb,
                                                const float* __restrict__ nw,
                                                float* __restrict__ out){
  extern __shared__ __align__(16) char smc[];
  __shared__ float scl[64];
  __nv_bfloat16* Ab = (__nv_bfloat16*)smc;
  const uint32_t O_B0 = 6*4608*2, O_B1 = O_B0 + 13824*2;
  uint32_t sbase = (uint32_t)__cvta_generic_to_shared(smc);
  int tid = threadIdx.x; int lane = tid&31, wid = tid>>5;
  int wm = wid&1, wn = wid>>1;
  int r0 = blockIdx.x*64; int bb = r0>>16; int p0 = r0&65535;

  for (int t=tid; t<1728; t+=256)
    cpa16(sbase + O_B0 + t*16, (const char*)(g_pk_pj) + t*16);
  CP_COMMIT();

  for (int idx=tid; idx<64*192; idx+=256){
    int px = idx/192, cc = idx - px*192;
    float v = (cc<180) ? g_y[(size_t)(r0+px)*180 + cc] : 0.f;
    __nv_bfloat16 h,l; cvhl(v,h,l);
    int t = cc>>6, k = cc&63;
    Ab[t*4608 + px*72 + k]     = h;
    Ab[(t+3)*4608 + px*72 + k] = l;
  }
  float c[2][6][4];
#pragma unroll
  for (int mt=0;mt<2;mt++)
#pragma unroll
    for (int nt=0;nt<6;nt++)
#pragma unroll
      for (int e=0;e<4;e++) c[mt][nt][e]=0.f;

  for (int i=0;i<6;i++){
    uint32_t bo = (i&1) ? O_B1 : O_B0;
    if (i<5){
      uint32_t bn = ((i+1)&1) ? O_B1 : O_B0;
      for (int t=tid; t<1728; t+=256)
        cpa16(sbase + bn + t*16, (const char*)(g_pk_pj + (i+1)*13824) + t*16);
      CP_COMMIT();
      CP_WAIT(1);
    } else {
      CP_WAIT(0);
    }
    __syncthreads();
    if (i<3){
      mma_pass<72,72,4>(sbase + (uint32_t)(i*4608*2),     sbase + bo, c, lane, wm, wn);
      mma_pass<72,72,4>(sbase + (uint32_t)((3+i)*4608*2), sbase + bo, c, lane, wm, wn);
    } else {
      mma_pass<72,72,4>(sbase + (uint32_t)((i-3)*4608*2), sbase + bo, c, lane, wm, wn);
    }
    __syncthreads();
  }
  float* stash = (float*)smc;
#pragma unroll
  for (int mt=0;mt<2;mt++){
    int r1 = wm*32 + mt*16 + (lane>>2);
#pragma unroll
    for (int nt=0;nt<6;nt++){
      int n0 = wn*48 + nt*8 + (lane&3)*2;
      if (n0 < 180){
        float b0=__ldg(pb+n0), b1=__ldg(pb+n0+1);
        stash[r1*181+n0]       = c[mt][nt][0]+b0;
        stash[r1*181+n0+1]     = c[mt][nt][1]+b1;
        stash[(r1+8)*181+n0]   = c[mt][nt][2]+b0;
        stash[(r1+8)*181+n0+1] = c[mt][nt][3]+b1;
      }
    }
  }
  __syncthreads();
  if (tid < 64){
    const float* row = stash + tid*181;
    float s = 0.f;
    for (int cc=0; cc<180; cc++){ float v = row[cc]; s += v*v; }
    scl[tid] = rsqrtf(s*(1.f/180.f) + 1.1920929e-07f);
  }
  __syncthreads();
  {
    int px = tid&63;
    int q = tid>>6;
    float sc = scl[px];
    for (int ci=q; ci<180; ci+=4){
      size_t a = ((size_t)(bb*180+ci))*NPIX + p0 + px;
      out[a] = x[a] + stash[px*181+ci]*sc*__ldg(nw+ci);
    }
  }
}

// =============== launch ===============
extern "C" void kernel_launch(void* const* d_in, const int* in_sizes, int n_in,
                              void* d_out, int out_size){
  const float* x     = (const float*)d_in[0];
  const float* w1    = (const float*)d_in[1];
  const float* b1    = (const float*)d_in[2];
  const float* w2    = (const float*)d_in[3];
  const float* b2    = (const float*)d_in[4];
  const float* w3    = (const float*)d_in[5];
  const float* b3    = (const float*)d_in[6];
  const float* lw    = (const float*)d_in[7];
  const float* lb    = (const float*)d_in[8];
  const float* sl_w  = (const float*)d_in[9];
  const float* sl_b  = (const float*)d_in[10];
  const float* ppw   = (const float*)d_in[11];
  const float* ppb   = (const float*)d_in[12];
  const float* ln1w  = (const float*)d_in[13];
  const float* ln1b  = (const float*)d_in[14];
  const float* l1w   = (const float*)d_in[15];
  const float* l1b   = (const float*)d_in[16];
  const float* ln2w  = (const float*)d_in[17];
  const float* ln2b  = (const float*)d_in[18];
  const float* l2w   = (const float*)d_in[19];
  const float* l2b   = (const float*)d_in[20];
  const float* ln3w  = (const float*)d_in[21];
  const float* ln3b  = (const float*)d_in[22];
  const float* l3w   = (const float*)d_in[23];
  const float* l3b   = (const float*)d_in[24];
  const float* pjw   = (const float*)d_in[25];
  const float* pjb   = (const float*)d_in[26];
  const float* nrmw  = (const float*)d_in[27];
  float* out = (float*)d_out;

  const int SM_M2  = 6*4608*2 + 2*13824*2;       // 110592 B
  const int SM_TH  = 7168*2*2 + 2*10752*2;       // 71680 B
  const int SM_CH  = 4*26624*2;                  // 212992 B
  cudaFuncSetAttribute(mega2,   cudaFuncAttributeMaxDynamicSharedMemorySize, SM_M2);
  cudaFuncSetAttribute(t_h3,    cudaFuncAttributeMaxDynamicSharedMemorySize, SM_TH);
  cudaFuncSetAttribute(attn_ch, cudaFuncAttributeMaxDynamicSharedMemorySize, SM_CH);
  cudaFuncSetAttribute(t_proj,  cudaFuncAttributeMaxDynamicSharedMemorySize, SM_M2);

  mega1<<<1760,256>>>(x, w1, b1, lw, pjw, w3,
                      ppw, ppb, ln1w, ln1b, l1w, l1b, ln2w, ln2b, l2w, l2b,
                      ln3w, ln3b, l3w, l3b);
  mega2<<<5504,256,SM_M2>>>(x, lb, w2, b2);
  t_h3<<<TOTPIX/64,256,SM_TH>>>(b3);
  attn_ch<<<NWIN,512,SM_CH>>>();                // launch #4 -> profiled
  attn_sp<<<NWIN,256>>>(sl_w, sl_b);
  t_proj<<<TOTPIX/64,256,SM_M2>>>(x, pjb, nrmw, out);
}

// round 12
// speedup vs baseline: 1.1715x; 1.0177x over previous
#include <cuda_runtime.h>
#include <cuda_bf16.h>
#include <math.h>
#include <stdint.h>

#define NBATCH 4
#define NCH    180
#define IMG    256
#define NPIX   (IMG*IMG)            // 65536
#define TOTPIX (NBATCH*NPIX)        // 262144
#define MIDC   36
#define NWIN   1024

// ---- scratch (device globals; no allocation allowed) ----
__device__ float g_h1[(size_t)TOTPIX*MIDC];
__device__ float g_h2[(size_t)TOTPIX*MIDC];
__device__ float g_qv[(size_t)TOTPIX*NCH];
__device__ float g_y [(size_t)TOTPIX*NCH];
__device__ float g_pos[961*6];
__device__ float g_rpb[6*256*64];
__device__ __align__(16) __nv_bfloat16 g_pk_lw[6*13824];
__device__ __align__(16) __nv_bfloat16 g_pk_pj[6*13824];
__device__ __align__(16) __nv_bfloat16 g_pk_w3[2*10752];

typedef unsigned long long u64;

__device__ __forceinline__ u64 pk2(float lo, float hi){
  u64 r; asm("mov.b64 %0,{%1,%2};" : "=l"(r) : "f"(lo), "f"(hi)); return r;
}
__device__ __forceinline__ u64 dup2(float v){ return pk2(v, v); }
__device__ __forceinline__ void up2(u64 v, float& lo, float& hi){
  asm("mov.b64 {%0,%1},%2;" : "=f"(lo), "=f"(hi) : "l"(v));
}
__device__ __forceinline__ u64 ffma2(u64 a, u64 b, u64 c){
  u64 d; asm("fma.rn.f32x2 %0,%1,%2,%3;" : "=l"(d) : "l"(a), "l"(b), "l"(c)); return d;
}
__device__ __forceinline__ u64 fmul2(u64 a, u64 b){
  u64 d; asm("mul.rn.f32x2 %0,%1,%2;" : "=l"(d) : "l"(a), "l"(b)); return d;
}
__device__ __forceinline__ float lrelu(float v){ return v >= 0.f ? v : 0.2f*v; }

__device__ __forceinline__ void cvhl(float v, __nv_bfloat16& h, __nv_bfloat16& l){
  h = __float2bfloat16(v);
  l = __float2bfloat16(v - __bfloat162float(h));
}

// ---- portable tensor-core primitives ----
#define MMA16816(c, a, b0, b1) \
  asm volatile("mma.sync.aligned.m16n8k16.row.col.f32.bf16.bf16.f32 " \
    "{%0,%1,%2,%3}, {%4,%5,%6,%7}, {%8,%9}, {%0,%1,%2,%3};" \
    : "+f"((c)[0]), "+f"((c)[1]), "+f"((c)[2]), "+f"((c)[3]) \
    : "r"((a)[0]), "r"((a)[1]), "r"((a)[2]), "r"((a)[3]), "r"(b0), "r"(b1))

__device__ __forceinline__ void ldsm_x4(uint32_t r[4], uint32_t saddr){
  asm volatile("ldmatrix.sync.aligned.m8n8.x4.shared.b16 {%0,%1,%2,%3}, [%4];"
    : "=r"(r[0]),"=r"(r[1]),"=r"(r[2]),"=r"(r[3]) : "r"(saddr));
}
__device__ __forceinline__ void ldsm_x4_t(uint32_t r[4], uint32_t saddr){
  asm volatile("ldmatrix.sync.aligned.m8n8.x4.trans.shared.b16 {%0,%1,%2,%3}, [%4];"
    : "=r"(r[0]),"=r"(r[1]),"=r"(r[2]),"=r"(r[3]) : "r"(saddr));
}
__device__ __forceinline__ void cpa16(uint32_t d, const void* s){
  asm volatile("cp.async.cg.shared.global [%0], [%1], 16;" :: "r"(d), "l"(s));
}
#define CP_COMMIT() asm volatile("cp.async.commit_group;" ::: "memory")
#define CP_WAIT(n)  asm volatile("cp.async.wait_group %0;" :: "n"(n) : "memory")

template<int SA, int SB, int NKS>
__device__ __forceinline__ void mma_pass(uint32_t aBase, uint32_t bBase,
                                         float c[2][6][4], int lane, int wm, int wn){
  uint32_t aoff[2], boff[3];
  int ar = (lane&7) + ((lane&8)?8:0);
  int ak = (lane&16)?8:0;
#pragma unroll
  for (int mt=0;mt<2;mt++) aoff[mt] = aBase + (uint32_t)(((wm*32+mt*16+ar)*SA + ak)*2);
  int br = (lane&7) + ((lane&16)?8:0);
  int bk = (lane&8)?8:0;
#pragma unroll
  for (int p=0;p<3;p++) boff[p] = bBase + (uint32_t)(((wn*48+p*16+br)*SB + bk)*2);

  uint32_t a[2][2][4], b[2][3][4];
  ldsm_x4(a[0][0], aoff[0]);
  ldsm_x4(a[0][1], aoff[1]);
#pragma unroll
  for (int p=0;p<3;p++) ldsm_x4(b[0][p], boff[p]);
#pragma unroll
  for (int ks=0;ks<NKS;ks++){
    int cur = ks&1, nxt = cur^1;
    if (ks+1 < NKS){
      ldsm_x4(a[nxt][0], aoff[0] + (ks+1)*32);
      ldsm_x4(a[nxt][1], aoff[1] + (ks+1)*32);
#pragma unroll
      for (int p=0;p<3;p++) ldsm_x4(b[nxt][p], boff[p] + (ks+1)*32);
    }
#pragma unroll
    for (int p=0;p<3;p++){
      MMA16816(c[0][2*p],   a[cur][0], b[cur][p][0], b[cur][p][1]);
      MMA16816(c[1][2*p],   a[cur][1], b[cur][p][0], b[cur][p][1]);
      MMA16816(c[0][2*p+1], a[cur][0], b[cur][p][2], b[cur][p][3]);
      MMA16816(c[1][2*p+1], a[cur][1], b[cur][p][2], b[cur][p][3]);
    }
  }
}

__device__ __forceinline__ void ln_relu11(const float* in, const float* w, const float* b, float* out){
  float m = 0.f;
#pragma unroll
  for (int j=0;j<11;j++) m += in[j];
  m *= (1.f/11.f);
  float var = 0.f;
#pragma unroll
  for (int j=0;j<11;j++){ float d = in[j]-m; var += d*d; }
  var *= (1.f/11.f);
  float inv = rsqrtf(var + 1e-5f);
#pragma unroll
  for (int j=0;j<11;j++) out[j] = fmaxf((in[j]-m)*inv*w[j] + b[j], 0.f);
}

// =============== MEGA1 ===============
__global__ void __launch_bounds__(256) mega1(
    const float* __restrict__ x,  const float* __restrict__ w1, const float* __restrict__ b1,
    const float* __restrict__ lw, const float* __restrict__ pjw, const float* __restrict__ w3,
    const float* __restrict__ pw, const float* __restrict__ pb,
    const float* __restrict__ ln1w, const float* __restrict__ ln1b,
    const float* __restrict__ p1w,  const float* __restrict__ p1b,
    const float* __restrict__ ln2w, const float* __restrict__ ln2b,
    const float* __restrict__ p2w,  const float* __restrict__ p2b,
    const float* __restrict__ ln3w, const float* __restrict__ ln3b,
    const float* __restrict__ p3w,  const float* __restrict__ p3b){
  __shared__ __align__(16) float ws[180*36];
  int gid = blockIdx.x;
  int tid = threadIdx.x;

  if (gid < 1024){
    for (int t=tid;t<180*36;t+=256) ws[t]=w1[t];
    __syncthreads();
    int r = gid*256 + tid;
    int b = r>>16; int p = r&65535;
    const float* xp = x + (size_t)b*NCH*NPIX + p;
    u64 acc2[18];
#pragma unroll
    for (int q=0;q<18;q++) acc2[q] = pk2(b1[2*q], b1[2*q+1]);
    for (int ci=0;ci<180;ci++){
      u64 v2 = dup2(xp[(size_t)ci*NPIX]);
      const ulonglong2* wr = (const ulonglong2*)(ws + ci*36);
#pragma unroll
      for (int q=0;q<9;q++){
        ulonglong2 w = wr[q];
        acc2[2*q]   = ffma2(v2, w.x, acc2[2*q]);
        acc2[2*q+1] = ffma2(v2, w.y, acc2[2*q+1]);
      }
    }
    float2* dst = (float2*)(g_h1 + (size_t)r*36);
#pragma unroll
    for (int q=0;q<18;q++){
      float lo,hi; up2(acc2[q], lo, hi);
      dst[q] = make_float2(lrelu(lo), lrelu(hi));
    }
  } else if (gid < 1672){
    int which = (gid >= 1348);
    const float* W = which ? pjw : lw;
    __nv_bfloat16* dst = which ? g_pk_pj : g_pk_lw;
    int base = which ? 1348 : 1024;
    int idx = (gid-base)*256 + tid;
    if (idx < 6*13824){
      int cc = idx/13824, r = idx - cc*13824, n = r/72, k = r - n*72;
      int half = cc/3, kc = cc - half*3;
      int kk = kc*64 + k;
      float v = (n<180 && k<64 && kk<180) ? W[kk*180+n] : 0.f;
      __nv_bfloat16 h, l; cvhl(v, h, l);
      dst[idx] = half ? l : h;
    }
  } else if (gid < 1756){
    int idx = (gid-1672)*256 + tid;
    if (idx < 2*10752){
      int cc = idx/10752, r = idx - cc*10752, n = r/56, k = r - n*56;
      float v = (n<180 && k<36) ? w3[k*180+n] : 0.f;
      __nv_bfloat16 h, l; cvhl(v, h, l);
      g_pk_w3[idx] = cc ? l : h;
    }
  } else {
    int n = (gid-1756)*256 + tid;
    if (n < 961){
      float i0 = (float)(n/31) - 15.f;
      float i1 = (float)(n%31) - 15.f;
      float p[11], t[11];
#pragma unroll
      for (int j=0;j<11;j++) p[j] = i0*pw[j] + i1*pw[11+j] + pb[j];
      ln_relu11(p, ln1w, ln1b, t);
#pragma unroll
      for (int k=0;k<11;k++){ float s=p1b[k];
#pragma unroll
        for (int j=0;j<11;j++) s += t[j]*p1w[j*11+k]; p[k]=s; }
      ln_relu11(p, ln2w, ln2b, t);
#pragma unroll
      for (int k=0;k<11;k++){ float s=p2b[k];
#pragma unroll
        for (int j=0;j<11;j++) s += t[j]*p2w[j*11+k]; p[k]=s; }
      ln_relu11(p, ln3w, ln3b, t);
#pragma unroll
      for (int k=0;k<6;k++){ float s=p3b[k];
#pragma unroll
        for (int j=0;j<11;j++) s += t[j]*p3w[j*6+k];
        g_pos[n*6+k] = s; }
    }
  }
}

// =============== MEGA2: t_lin + conv3 + rpb ===============
__global__ void __launch_bounds__(256,2) mega2(const float* __restrict__ x,
                                               const float* __restrict__ lb,
                                               const float* __restrict__ w2,
                                               const float* __restrict__ b2){
  extern __shared__ __align__(16) char smc[];
  int gid = blockIdx.x;
  int tid = threadIdx.x;

  if (gid < 4096){
    __nv_bfloat16* Ab = (__nv_bfloat16*)smc;
    const uint32_t O_B0 = 6*4608*2, O_B1 = O_B0 + 13824*2;
    uint32_t sbase = (uint32_t)__cvta_generic_to_shared(smc);
    int lane = tid&31, wid = tid>>5;
    int wm = wid&1, wn = wid>>1;
    int r0 = gid*64; int bb = r0>>16; int p0 = r0&65535;

    for (int t=tid; t<1728; t+=256)
      cpa16(sbase + O_B0 + t*16, (const char*)(g_pk_lw) + t*16);
    CP_COMMIT();

    for (int idx=tid; idx<192*64; idx+=256){
      int c = idx>>6, px = idx&63;
      float v = (c<180) ? x[((size_t)(bb*180+c))*NPIX + p0+px] : 0.f;
      __nv_bfloat16 h,l; cvhl(v,h,l);
      int t = c>>6, k = c&63;
      Ab[t*4608 + px*72 + k]     = h;
      Ab[(t+3)*4608 + px*72 + k] = l;
    }
    float c[2][6][4];
#pragma unroll
    for (int mt=0;mt<2;mt++)
#pragma unroll
      for (int nt=0;nt<6;nt++)
#pragma unroll
        for (int e=0;e<4;e++) c[mt][nt][e]=0.f;

    for (int i=0;i<6;i++){
      uint32_t bo = (i&1) ? O_B1 : O_B0;
      if (i<5){
        uint32_t bn = ((i+1)&1) ? O_B1 : O_B0;
        for (int t=tid; t<1728; t+=256)
          cpa16(sbase + bn + t*16, (const char*)(g_pk_lw + (i+1)*13824) + t*16);
        CP_COMMIT();
        CP_WAIT(1);
      } else {
        CP_WAIT(0);
      }
      __syncthreads();
      if (i<3){
        mma_pass<72,72,4>(sbase + (uint32_t)(i*4608*2),     sbase + bo, c, lane, wm, wn);
        mma_pass<72,72,4>(sbase + (uint32_t)((3+i)*4608*2), sbase + bo, c, lane, wm, wn);
      } else {
        mma_pass<72,72,4>(sbase + (uint32_t)((i-3)*4608*2), sbase + bo, c, lane, wm, wn);
      }
      __syncthreads();
    }
    float* stash = (float*)smc;
#pragma unroll
    for (int mt=0;mt<2;mt++){
      int r1 = wm*32 + mt*16 + (lane>>2);
#pragma unroll
      for (int nt=0;nt<6;nt++){
        int n0 = wn*48 + nt*8 + (lane&3)*2;
        if (n0 < 180){
          float bl0=__ldg(lb+n0), bl1=__ldg(lb+n0+1);
          stash[r1*181+n0]       = c[mt][nt][0]+bl0;
          stash[r1*181+n0+1]     = c[mt][nt][1]+bl1;
          stash[(r1+8)*181+n0]   = c[mt][nt][2]+bl0;
          stash[(r1+8)*181+n0+1] = c[mt][nt][3]+bl1;
        }
      }
    }
    __syncthreads();
    int f = tid;
    int px = f/180, co = f - px*180;
    for (; f < 64*180; f += 256){
      g_y[(size_t)r0*180 + f] = stash[px*181+co];
      co += 256; if (co >= 180){ co -= 180; px++; if (co >= 180){ co -= 180; px++; } }
    }
  } else if (gid < 5120){
    float* ins = (float*)smc;
    float* wsh = (float*)smc + 11988;
    int cg = gid - 4096;
    int b = cg>>8; int hy0 = ((cg>>4)&15)*16, wx0 = (cg&15)*16;
    for (int t=tid;t<18*18*36;t+=256){
      int ci = t%36; int rc = t/36; int col = rc%18; int row = rc/18;
      int gh = hy0+row-1, gw = wx0+col-1;
      float v = 0.f;
      if (gh>=0 && gh<IMG && gw>=0 && gw<IMG)
        v = g_h1[((size_t)(b*IMG+gh)*IMG+gw)*36 + ci];
      ins[(row*18+col)*37+ci] = v;
    }
    for (int t=tid;t<9*36*36;t+=256) wsh[t] = w2[t];
    __syncthreads();
    int tx = tid&15, ty = tid>>4;
    float acc[36];
#pragma unroll
    for (int co=0;co<36;co++) acc[co] = b2[co];
    for (int dy=0;dy<3;dy++)
      for (int dx=0;dx<3;dx++){
        const float* wp = wsh + (dy*3+dx)*36*36;
        const float* ip = ins + ((ty+dy)*18 + tx+dx)*37;
        for (int ci=0;ci<36;ci++){
          float v = ip[ci];
          const float* wr = wp + ci*36;
#pragma unroll
          for (int co=0;co<36;co++) acc[co] += v*wr[co];
        }
      }
    size_t o = ((size_t)(b*IMG+hy0+ty)*IMG + wx0+tx)*36;
    float4* dst = (float4*)(g_h2 + o);
#pragma unroll
    for (int q=0;q<9;q++){
      float4 r; r.x=lrelu(acc[q*4]); r.y=lrelu(acc[q*4+1]); r.z=lrelu(acc[q*4+2]); r.w=lrelu(acc[q*4+3]);
      dst[q]=r;
    }
  } else {
    int idx = (gid-5120)*256 + tid;
    if (idx < 6*256*64){
      int nh = idx/16384;
      int r  = idx - nh*16384;
      int l  = r>>6;
      int m  = r&63;
      int rl = l>>4, cl = l&15;
      int mh = m>>3, mw = m&7;
      float s = 0.f;
#pragma unroll
      for (int rh=0;rh<2;rh++)
#pragma unroll
        for (int rw=0;rw<2;rw++){
          int r2 = mh*2+rh, c2 = mw*2+rw;
          int k = (rl-r2+15)*31 + (cl-c2+15);
          s += g_pos[k*6+nh];
        }
      g_rpb[idx] = 0.25f*s;
    }
  }
}

// =============== T2: t_h3 ===============
__global__ void __launch_bounds__(256,2) t_h3(const float* __restrict__ b3){
  extern __shared__ __align__(16) char smc[];
  __nv_bfloat16* Ab = (__nv_bfloat16*)smc;
  const uint32_t O_B = 7168*2;
  uint32_t sbase = (uint32_t)__cvta_generic_to_shared(smc);
  int tid = threadIdx.x; int lane = tid&31, wid = tid>>5;
  int wm = wid&1, wn = wid>>1;
  int r0 = blockIdx.x*64;

  for (int t=tid; t<2688; t+=256)
    cpa16(sbase + O_B + t*16, (const char*)(g_pk_w3) + t*16);
  CP_COMMIT();

  for (int idx=tid; idx<64*48; idx+=256){
    int px = idx/48, cc = idx - px*48;
    float v = (cc<36) ? g_h2[(size_t)(r0+px)*36 + cc] : 0.f;
    __nv_bfloat16 h,l; cvhl(v,h,l);
    Ab[px*56 + cc]        = h;
    Ab[3584 + px*56 + cc] = l;
  }
  CP_WAIT(0);
  __syncthreads();
  float c[2][6][4];
#pragma unroll
  for (int mt=0;mt<2;mt++)
#pragma unroll
    for (int nt=0;nt<6;nt++)
#pragma unroll
      for (int e=0;e<4;e++) c[mt][nt][e]=0.f;

  mma_pass<56,56,3>(sbase,           sbase + O_B,           c, lane, wm, wn);
  mma_pass<56,56,3>(sbase + 3584*2,  sbase + O_B,           c, lane, wm, wn);
  mma_pass<56,56,3>(sbase,           sbase + O_B + 10752*2, c, lane, wm, wn);
  __syncthreads();
  float* stash = (float*)smc;
#pragma unroll
  for (int mt=0;mt<2;mt++){
    int r1 = wm*32 + mt*16 + (lane>>2);
#pragma unroll
    for (int nt=0;nt<6;nt++){
      int n0 = wn*48 + nt*8 + (lane&3)*2;
      if (n0 < 180){
        float b30=__ldg(b3+n0), b31=__ldg(b3+n0+1);
        stash[r1*181+n0]       = c[mt][nt][0]+b30;
        stash[r1*181+n0+1]     = c[mt][nt][1]+b31;
        stash[(r1+8)*181+n0]   = c[mt][nt][2]+b30;
        stash[(r1+8)*181+n0+1] = c[mt][nt][3]+b31;
      }
    }
  }
  __syncthreads();
  {
    int f = tid;
    int px = f/180, co = f - px*180;
    for (; f < 64*180; f += 256){
      g_qv[(size_t)r0*180 + f] = stash[px*181+co] * g_y[(size_t)r0*180 + f];
      co += 256; if (co >= 180){ co -= 180; px++; if (co >= 180){ co -= 180; px++; } }
    }
  }
}

// =============== attn_sp: 2-pixel vp reuse (halved LDS traffic) ===============
// 256 threads: thread t -> pixels (t&127, (t&127)+128), heads (t>>7)*3 .. +2
__global__ void __launch_bounds__(256,2) attn_sp(const float* __restrict__ sl_w,
                                                 const float* __restrict__ sl_b){
  __shared__ float vp[6144];
  int tid = threadIdx.x;
  int pr = tid & 127;
  int hg = tid >> 7;        // 0 or 1
  int bw = blockIdx.x;
  int b = bw>>8, wy = (bw>>4)&15, wx = bw&15;
  size_t pix0 = ((size_t)(b*IMG + wy*16))*IMG + wx*16;
  int l0 = pr, l1 = pr + 128;
  size_t pixA = pix0 + (size_t)(l0>>4)*IMG + (l0&15);
  size_t pixB = pix0 + (size_t)(l1>>4)*IMG + (l1&15);

  // P2: vp from global V
  float slw0=__ldg(sl_w), slw1=__ldg(sl_w+1), slw2=__ldg(sl_w+2), slw3=__ldg(sl_w+3), slb=__ldg(sl_b);
  for (int idx=tid; idx<6144; idx+=256){
    int nh = idx>>10; int r = idx & 1023; int m = r>>4; int hd = r&15;
    float val = 0.f;
    if (hd < 15){
      int mh = m>>3, mw = m&7; int ch = 90 + nh*15 + hd;
      size_t pA = pix0 + (size_t)(mh*2)*IMG + mw*2;
      val = slb + slw0*__ldg(g_qv + pA*180 + ch)
                + slw1*__ldg(g_qv + (pA+1)*180 + ch)
                + slw2*__ldg(g_qv + (pA+IMG)*180 + ch)
                + slw3*__ldg(g_qv + (pA+IMG+1)*180 + ch);
    }
    vp[idx] = val;
  }
  __syncthreads();

  const float* qrowA = g_qv + pixA*180;
  const float* qrowB = g_qv + pixB*180;
  float* ydstA = g_y + pixA*180;
  float* ydstB = g_y + pixB*180;

#pragma unroll
  for (int e=0; e<3; e++){
    int nh = hg*3 + e;
    u64 qa[8], qb[8];
    {
      float qs[15];
#pragma unroll
      for (int hd=0;hd<15;hd++) qs[hd] = __ldg(qrowA + nh*15 + hd);
#pragma unroll
      for (int p=0;p<7;p++) qa[p] = pk2(qs[2*p], qs[2*p+1]);
      qa[7] = pk2(qs[14], 0.f);
#pragma unroll
      for (int hd=0;hd<15;hd++) qs[hd] = __ldg(qrowB + nh*15 + hd);
#pragma unroll
      for (int p=0;p<7;p++) qb[p] = pk2(qs[2*p], qs[2*p+1]);
      qb[7] = pk2(qs[14], 0.f);
    }
    const float* vph = vp + (nh<<10);
    const float* rpbA = g_rpb + ((size_t)((nh<<8) + l0))*64;
    const float* rpbB = g_rpb + ((size_t)((nh<<8) + l1))*64;
    u64 xa[8], xb[8];
#pragma unroll
    for (int p=0;p<8;p++){ xa[p]=0ull; xb[p]=0ull; }
    for (int m0=0;m0<64;m0+=4){
      float4 rba = *(const float4*)(rpbA + m0);
      float4 rbb = *(const float4*)(rpbB + m0);
      float rav[4] = {rba.x, rba.y, rba.z, rba.w};
      float rbv[4] = {rbb.x, rbb.y, rbb.z, rbb.w};
#pragma unroll
      for (int t=0;t<4;t++){
        const ulonglong2* vpp = (const ulonglong2*)(vph + ((m0+t)<<4));
        ulonglong2 wA = vpp[0], wB = vpp[1], wC = vpp[2], wD = vpp[3];
        // dot for pixel A
        u64 da = fmul2(qa[0], wA.x);
        da = ffma2(qa[1], wA.y, da);
        da = ffma2(qa[2], wB.x, da);
        da = ffma2(qa[3], wB.y, da);
        da = ffma2(qa[4], wC.x, da);
        da = ffma2(qa[5], wC.y, da);
        da = ffma2(qa[6], wD.x, da);
        da = ffma2(qa[7], wD.y, da);
        // dot for pixel B
        u64 db = fmul2(qb[0], wA.x);
        db = ffma2(qb[1], wA.y, db);
        db = ffma2(qb[2], wB.x, db);
        db = ffma2(qb[3], wB.y, db);
        db = ffma2(qb[4], wC.x, db);
        db = ffma2(qb[5], wC.y, db);
        db = ffma2(qb[6], wD.x, db);
        db = ffma2(qb[7], wD.y, db);
        float la,ha; up2(da, la, ha);
        float lb2,hb2; up2(db, lb2, hb2);
        u64 sa = dup2((la+ha)*(1.f/15.f) + rav[t]);
        u64 sb = dup2((lb2+hb2)*(1.f/15.f) + rbv[t]);
        xa[0] = ffma2(sa, wA.x, xa[0]);
        xa[1] = ffma2(sa, wA.y, xa[1]);
        xa[2] = ffma2(sa, wB.x, xa[2]);
        xa[3] = ffma2(sa, wB.y, xa[3]);
        xa[4] = ffma2(sa, wC.x, xa[4]);
        xa[5] = ffma2(sa, wC.y, xa[5]);
        xa[6] = ffma2(sa, wD.x, xa[6]);
        xa[7] = ffma2(sa, wD.y, xa[7]);
        xb[0] = ffma2(sb, wA.x, xb[0]);
        xb[1] = ffma2(sb, wA.y, xb[1]);
        xb[2] = ffma2(sb, wB.x, xb[2]);
        xb[3] = ffma2(sb, wB.y, xb[3]);
        xb[4] = ffma2(sb, wC.x, xb[4]);
        xb[5] = ffma2(sb, wC.y, xb[5]);
        xb[6] = ffma2(sb, wD.x, xb[6]);
        xb[7] = ffma2(sb, wD.y, xb[7]);
      }
    }
#pragma unroll
    for (int p=0;p<7;p++){
      float lo,hi; up2(xa[p], lo, hi);
      ydstA[nh*15+2*p] = lo; ydstA[nh*15+2*p+1] = hi;
    }
    { float lo,hi; up2(xa[7], lo, hi); ydstA[nh*15+14] = lo; }
#pragma unroll
    for (int p=0;p<7;p++){
      float lo,hi; up2(xb[p], lo, hi);
      ydstB[nh*15+2*p] = lo; ydstB[nh*15+2*p+1] = hi;
    }
    { float lo,hi; up2(xb[7], lo, hi); ydstB[nh*15+14] = lo; }
  }
}

// =============== attn_ch: channel attention via mma (R11 form) ===============
__global__ void __launch_bounds__(512) attn_ch(){
  extern __shared__ __align__(16) char smc[];
  uint32_t sbase = (uint32_t)__cvta_generic_to_shared(smc);
  __nv_bfloat16* sm16 = (__nv_bfloat16*)smc;
  int tid = threadIdx.x; int lane = tid&31; int w = tid>>5;
  int bw = blockIdx.x;
  int b = bw>>8, wy = (bw>>4)&15, wx = bw&15;
  size_t pix0 = ((size_t)(b*IMG + wy*16))*IMG + wx*16;

  const int QH=0, QL=26624, VH=53248, VL=79872;
  for (int t=tid; t<256*14; t+=512){
    int px = t/14, c = 90 + t%14;
    sm16[QH + px*104 + c] = __nv_bfloat16(0.f);
    sm16[QL + px*104 + c] = __nv_bfloat16(0.f);
    sm16[VH + px*104 + c] = __nv_bfloat16(0.f);
    sm16[VL + px*104 + c] = __nv_bfloat16(0.f);
  }
  for (int idx=tid; idx<256*45; idx+=512){
    int px = idx/45, q4 = idx - px*45;
    size_t pix = pix0 + (size_t)(px>>4)*IMG + (px&15);
    float4 v4 = *(const float4*)(g_qv + pix*180 + q4*4);
    float vals[4] = {v4.x, v4.y, v4.z, v4.w};
#pragma unroll
    for (int e=0;e<4;e++){
      int c = q4*4 + e;
      __nv_bfloat16 h,l; cvhl(vals[e], h, l);
      if (c < 90){
        sm16[QH + px*104 + c] = h;
        sm16[QL + px*104 + c] = l;
      } else {
        sm16[VH + px*104 + (c-90)] = h;
        sm16[VL + px*104 + (c-90)] = l;
      }
    }
  }
  __syncthreads();

  float c1[6][4];
#pragma unroll
  for (int nt=0;nt<6;nt++)
#pragma unroll
    for (int e=0;e<4;e++) c1[nt][e]=0.f;
  if (w < 12){
    int wm = w % 6, wn = w / 6;
    int arT = (lane&7) + ((lane&16)?8:0);
    int akT = (lane&8)?8:0;
    int brT = (lane&7) + ((lane&8)?8:0);
    int bkT = (lane&16)?8:0;
    const int passes[3][2] = {{QH,VH},{QL,VH},{QH,VL}};
#pragma unroll
    for (int ps=0; ps<3; ps++){
      uint32_t aoff = sbase + (uint32_t)((passes[ps][0] + arT*104 + wm*16 + akT)*2);
      uint32_t boff[3];
#pragma unroll
      for (int p=0;p<3;p++)
        boff[p] = sbase + (uint32_t)((passes[ps][1] + brT*104 + wn*48 + p*16 + bkT)*2);
      for (int ks=0;ks<16;ks++){
        uint32_t a4[4];
        ldsm_x4_t(a4, aoff + ks*16*208);
#pragma unroll
        for (int p=0;p<3;p++){
          uint32_t b4[4];
          ldsm_x4_t(b4, boff[p] + ks*16*208);
          MMA16816(c1[2*p],   a4, b4[0], b4[1]);
          MMA16816(c1[2*p+1], a4, b4[2], b4[3]);
        }
      }
    }
  }
  __syncthreads();

  const int CMH=0, CML=9984;
  {
    uint4* z = (uint4*)smc;
    for (int t=tid; t<2496; t+=512) z[t] = make_uint4(0,0,0,0);
  }
  __syncthreads();
  if (w < 12){
    int wm = w % 6, wn = w / 6;
    int c0 = wm*16 + (lane>>2);
#pragma unroll
    for (int nt=0;nt<6;nt++){
      int d0 = wn*48 + nt*8 + (lane&3)*2;
      if (d0 < 90){
#pragma unroll
        for (int half=0; half<2; half++){
          int cc = c0 + half*8;
          if (cc < 90){
            float v0 = c1[nt][half*2]   * (1.f/256.f);
            float v1 = c1[nt][half*2+1] * (1.f/256.f);
            __nv_bfloat16 h0,l0,h1,l1; cvhl(v0,h0,l0); cvhl(v1,h1,l1);
            sm16[CMH + cc*104 + d0]   = h0;
            sm16[CMH + cc*104 + d0+1] = h1;
            sm16[CML + cc*104 + d0]   = l0;
            sm16[CML + cc*104 + d0+1] = l1;
          }
        }
      }
    }
  }
  __syncthreads();

  float c2[12][4];
#pragma unroll
  for (int nt=0;nt<12;nt++)
#pragma unroll
    for (int e=0;e<4;e++) c2[nt][e]=0.f;
  {
    int ar = (lane&7) + ((lane&8)?8:0);
    int ak = (lane&16)?8:0;
    int br = (lane&7) + ((lane&16)?8:0);
    int bk = (lane&8)?8:0;
    const int passes[3][2] = {{VH,CMH},{VL,CMH},{VH,CML}};
#pragma unroll
    for (int ps=0; ps<3; ps++){
      uint32_t aoff = sbase + (uint32_t)((passes[ps][0] + (w*16+ar)*104 + ak)*2);
      uint32_t boff[6];
#pragma unroll
      for (int p=0;p<6;p++)
        boff[p] = sbase + (uint32_t)((passes[ps][1] + (p*16+br)*104 + bk)*2);
      for (int ks=0;ks<6;ks++){
        uint32_t a4[4];
        ldsm_x4(a4, aoff + ks*32);
#pragma unroll
        for (int p=0;p<6;p++){
          uint32_t b4[4];
          ldsm_x4(b4, boff[p] + ks*32);
          MMA16816(c2[2*p],   a4, b4[0], b4[1]);
          MMA16816(c2[2*p+1], a4, b4[2], b4[3]);
        }
      }
    }
  }

  {
    int r1 = w*16 + (lane>>2);
#pragma unroll
    for (int half=0; half<2; half++){
      int l = r1 + half*8;
      size_t pix = pix0 + (size_t)(l>>4)*IMG + (l&15);
      float* ydst = g_y + pix*180 + 90;
#pragma unroll
      for (int nt=0;nt<12;nt++){
        int n0 = nt*8 + (lane&3)*2;
        if (n0 < 90)
          *(float2*)(ydst + n0) = make_float2(c2[nt][half*2], c2[nt][half*2+1]);
      }
    }
  }
}

// =============== T3: t_proj ===============
__global__ void __launch_bounds__(256,2) t_proj(const float* __restrict__ x,
                                                const float* __restrict__ pb,
                                                const float* __restrict__ nw,
                                                float* __restrict__ out){
  extern __shared__ __align__(16) char smc[];
  __shared__ float scl[64];
  __nv_bfloat16* Ab = (__nv_bfloat16*)smc;
  const uint32_t O_B0 = 6*4608*2, O_B1 = O_B0 + 13824*2;
  uint32_t sbase = (uint32_t)__cvta_generic_to_shared(smc);
  int tid = threadIdx.x; int lane = tid&31, wid = tid>>5;
  int wm = wid&1, wn = wid>>1;
  int r0 = blockIdx.x*64; int bb = r0>>16; int p0 = r0&65535;

  for (int t=tid; t<1728; t+=256)
    cpa16(sbase + O_B0 + t*16, (const char*)(g_pk_pj) + t*16);
  CP_COMMIT();

  for (int idx=tid; idx<64*192; idx+=256){
    int px = idx/192, cc = idx - px*192;
    float v = (cc<180) ? g_y[(size_t)(r0+px)*180 + cc] : 0.f;
    __nv_bfloat16 h,l; cvhl(v,h,l);
    int t = cc>>6, k = cc&63;
    Ab[t*4608 + px*72 + k]     = h;
    Ab[(t+3)*4608 + px*72 + k] = l;
  }
  float c[2][6][4];
#pragma unroll
  for (int mt=0;mt<2;mt++)
#pragma unroll
    for (int nt=0;nt<6;nt++)
#pragma unroll
      for (int e=0;e<4;e++) c[mt][nt][e]=0.f;

  for (int i=0;i<6;i++){
    uint32_t bo = (i&1) ? O_B1 : O_B0;
    if (i<5){
      uint32_t bn = ((i+1)&1) ? O_B1 : O_B0;
      for (int t=tid; t<1728; t+=256)
        cpa16(sbase + bn + t*16, (const char*)(g_pk_pj + (i+1)*13824) + t*16);
      CP_COMMIT();
      CP_WAIT(1);
    } else {
      CP_WAIT(0);
    }
    __syncthreads();
    if (i<3){
      mma_pass<72,72,4>(sbase + (uint32_t)(i*4608*2),     sbase + bo, c, lane, wm, wn);
      mma_pass<72,72,4>(sbase + (uint32_t)((3+i)*4608*2), sbase + bo, c, lane, wm, wn);
    } else {
      mma_pass<72,72,4>(sbase + (uint32_t)((i-3)*4608*2), sbase + bo, c, lane, wm, wn);
    }
    __syncthreads();
  }
  float* stash = (float*)smc;
#pragma unroll
  for (int mt=0;mt<2;mt++){
    int r1 = wm*32 + mt*16 + (lane>>2);
#pragma unroll
    for (int nt=0;nt<6;nt++){
      int n0 = wn*48 + nt*8 + (lane&3)*2;
      if (n0 < 180){
        float b0=__ldg(pb+n0), b1=__ldg(pb+n0+1);
        stash[r1*181+n0]       = c[mt][nt][0]+b0;
        stash[r1*181+n0+1]     = c[mt][nt][1]+b1;
        stash[(r1+8)*181+n0]   = c[mt][nt][2]+b0;
        stash[(r1+8)*181+n0+1] = c[mt][nt][3]+b1;
      }
    }
  }
  __syncthreads();
  if (tid < 64){
    const float* row = stash + tid*181;
    float s = 0.f;
    for (int cc=0; cc<180; cc++){ float v = row[cc]; s += v*v; }
    scl[tid] = rsqrtf(s*(1.f/180.f) + 1.1920929e-07f);
  }
  __syncthreads();
  {
    int px = tid&63;
    int q = tid>>6;
    float sc = scl[px];
    for (int ci=q; ci<180; ci+=4){
      size_t a = ((size_t)(bb*180+ci))*NPIX + p0 + px;
      out[a] = x[a] + stash[px*181+ci]*sc*__ldg(nw+ci);
    }
  }
}

// =============== launch ===============
extern "C" void kernel_launch(void* const* d_in, const int* in_sizes, int n_in,
                              void* d_out, int out_size){
  const float* x     = (const float*)d_in[0];
  const float* w1    = (const float*)d_in[1];
  const float* b1    = (const float*)d_in[2];
  const float* w2    = (const float*)d_in[3];
  const float* b2    = (const float*)d_in[4];
  const float* w3    = (const float*)d_in[5];
  const float* b3    = (const float*)d_in[6];
  const float* lw    = (const float*)d_in[7];
  const float* lb    = (const float*)d_in[8];
  const float* sl_w  = (const float*)d_in[9];
  const float* sl_b  = (const float*)d_in[10];
  const float* ppw   = (const float*)d_in[11];
  const float* ppb   = (const float*)d_in[12];
  const float* ln1w  = (const float*)d_in[13];
  const float* ln1b  = (const float*)d_in[14];
  const float* l1w   = (const float*)d_in[15];
  const float* l1b   = (const float*)d_in[16];
  const float* ln2w  = (const float*)d_in[17];
  const float* ln2b  = (const float*)d_in[18];
  const float* l2w   = (const float*)d_in[19];
  const float* l2b   = (const float*)d_in[20];
  const float* ln3w  = (const float*)d_in[21];
  const float* ln3b  = (const float*)d_in[22];
  const float* l3w   = (const float*)d_in[23];
  const float* l3b   = (const float*)d_in[24];
  const float* pjw   = (const float*)d_in[25];
  const float* pjb   = (const float*)d_in[26];
  const float* nrmw  = (const float*)d_in[27];
  float* out = (float*)d_out;

  const int SM_M2  = 6*4608*2 + 2*13824*2;       // 110592 B
  const int SM_TH  = 7168*2*2 + 2*10752*2;       // 71680 B
  const int SM_CH  = 4*26624*2;                  // 212992 B
  cudaFuncSetAttribute(mega2,   cudaFuncAttributeMaxDynamicSharedMemorySize, SM_M2);
  cudaFuncSetAttribute(t_h3,    cudaFuncAttributeMaxDynamicSharedMemorySize, SM_TH);
  cudaFuncSetAttribute(attn_ch, cudaFuncAttributeMaxDynamicSharedMemorySize, SM_CH);
  cudaFuncSetAttribute(t_proj,  cudaFuncAttributeMaxDynamicSharedMemorySize, SM_M2);

  mega1<<<1760,256>>>(x, w1, b1, lw, pjw, w3,
                      ppw, ppb, ln1w, ln1b, l1w, l1b, ln2w, ln2b, l2w, l2b,
                      ln3w, ln3b, l3w, l3b);
  mega2<<<5504,256,SM_M2>>>(x, lb, w2, b2);
  t_h3<<<TOTPIX/64,256,SM_TH>>>(b3);
  attn_sp<<<NWIN,256>>>(sl_w, sl_b);            // launch #4 -> profiled
  attn_ch<<<NWIN,512,SM_CH>>>();
  t_proj<<<TOTPIX/64,256,SM_M2>>>(x, pjb, nrmw, out);
}